// round 4
// baseline (speedup 1.0000x reference)
#include <cuda_runtime.h>
#include <math.h>

// Problem constants
#define B_   2
#define S_   2048
#define D_   2048
#define NH_  16
#define HD_  128
#define M_   (B_*S_)          // 4096 total rows

// ---------------------------------------------------------------------------
// Scratch (static device globals — no runtime allocation allowed)
// ---------------------------------------------------------------------------
__device__ float g_q[(size_t)M_ * D_];
__device__ float g_k[(size_t)M_ * D_];
__device__ float g_v[(size_t)M_ * D_];
__device__ float g_attn[(size_t)M_ * D_];

// ---------------------------------------------------------------------------
// tf32 helpers (3xTF32 = near-fp32 precision on the tensor pipe)
// ---------------------------------------------------------------------------
__device__ __forceinline__ void split_tf32(float x, unsigned &hi, unsigned &lo) {
    asm("cvt.rna.tf32.f32 %0, %1;" : "=r"(hi) : "f"(x));
    float r = x - __uint_as_float(hi);
    asm("cvt.rna.tf32.f32 %0, %1;" : "=r"(lo) : "f"(r));
}

__device__ __forceinline__ void mma_tf32(float* c, const unsigned* a, const unsigned* b) {
    asm volatile(
        "mma.sync.aligned.m16n8k8.row.col.f32.tf32.tf32.f32 "
        "{%0,%1,%2,%3}, {%4,%5,%6,%7}, {%8,%9}, {%0,%1,%2,%3};"
        : "+f"(c[0]), "+f"(c[1]), "+f"(c[2]), "+f"(c[3])
        : "r"(a[0]), "r"(a[1]), "r"(a[2]), "r"(a[3]),
          "r"(b[0]), "r"(b[1]));
}

// ---------------------------------------------------------------------------
// GEMM (TN) via tf32 tensor cores, 3xTF32 precision recovery.
//   C[m, n] = sum_d A[m, d] * W[n, d]
//   A: [4096, 2048] rm, W: [2048, 2048] rm, C: [4096, 2048] rm
// Optional fused RoPE epilogue (Q and K projections).
// Block: 128x128 tile, BK=32, 256 threads = 8 warps (2 m x 4 n).
// Warp tile 64x32 -> 4x4 m16n8 fragments.
// ---------------------------------------------------------------------------
#define GBK 32
#define AS_STRIDE 36

__global__ __launch_bounds__(256) void gemm_tf32_rope(
    const float* __restrict__ A, const float* __restrict__ W,
    float* __restrict__ C, const float* __restrict__ fc, int applyRope)
{
    __shared__ __align__(16) float As[128][AS_STRIDE];
    __shared__ __align__(16) float Bs[128][AS_STRIDE];

    const int tid  = threadIdx.x;
    const int warp = tid >> 5;
    const int lane = tid & 31;
    const int wm   = warp >> 2;      // 0..1
    const int wn   = warp & 3;       // 0..3
    const int g    = lane >> 2;      // groupID 0..7
    const int tg   = lane & 3;       // thread-in-group 0..3

    const int bm = blockIdx.x * 128;
    const int bn = blockIdx.y * 128;

    float acc[4][4][4];
    #pragma unroll
    for (int i = 0; i < 4; i++)
        #pragma unroll
        for (int j = 0; j < 4; j++)
            #pragma unroll
            for (int f = 0; f < 4; f++) acc[i][j][f] = 0.f;

    // Global load mapping: 4 rows/warp, 8 lanes span 32 consecutive floats.
    const int lrow = tid >> 3;         // 0..31
    const int lk   = (tid & 7) << 2;   // 0,4,...,28

    float4 pa[4], pb[4];

    // prefetch tile 0
    #pragma unroll
    for (int p = 0; p < 4; p++) {
        int r = lrow + p * 32;
        pa[p] = *(const float4*)(A + (size_t)(bm + r) * D_ + lk);
        pb[p] = *(const float4*)(W + (size_t)(bn + r) * D_ + lk);
    }

    for (int kt = 0; kt < D_; kt += GBK) {
        __syncthreads();   // previous compute done before overwrite
        #pragma unroll
        for (int p = 0; p < 4; p++) {
            int r = lrow + p * 32;
            *(float4*)&As[r][lk] = pa[p];
            *(float4*)&Bs[r][lk] = pb[p];
        }
        __syncthreads();

        if (kt + GBK < D_) {
            #pragma unroll
            for (int p = 0; p < 4; p++) {
                int r = lrow + p * 32;
                pa[p] = *(const float4*)(A + (size_t)(bm + r) * D_ + kt + GBK + lk);
                pb[p] = *(const float4*)(W + (size_t)(bn + r) * D_ + kt + GBK + lk);
            }
        }

        #pragma unroll
        for (int ks = 0; ks < 4; ks++) {
            const int kb = ks * 8;
            unsigned ahi[4][4], alo[4][4];
            #pragma unroll
            for (int mt = 0; mt < 4; mt++) {
                const int m0 = wm * 64 + mt * 16;
                float a0 = As[m0 + g     ][kb + tg];
                float a1 = As[m0 + 8 + g ][kb + tg];
                float a2 = As[m0 + g     ][kb + 4 + tg];
                float a3 = As[m0 + 8 + g ][kb + 4 + tg];
                split_tf32(a0, ahi[mt][0], alo[mt][0]);
                split_tf32(a1, ahi[mt][1], alo[mt][1]);
                split_tf32(a2, ahi[mt][2], alo[mt][2]);
                split_tf32(a3, ahi[mt][3], alo[mt][3]);
            }
            unsigned bhi[4][2], blo[4][2];
            #pragma unroll
            for (int nt = 0; nt < 4; nt++) {
                const int n0 = wn * 32 + nt * 8;
                float b0 = Bs[n0 + g][kb + tg];
                float b1 = Bs[n0 + g][kb + 4 + tg];
                split_tf32(b0, bhi[nt][0], blo[nt][0]);
                split_tf32(b1, bhi[nt][1], blo[nt][1]);
            }
            #pragma unroll
            for (int mt = 0; mt < 4; mt++)
                #pragma unroll
                for (int nt = 0; nt < 4; nt++) {
                    mma_tf32(acc[mt][nt], ahi[mt], blo[nt]);
                    mma_tf32(acc[mt][nt], alo[mt], bhi[nt]);
                    mma_tf32(acc[mt][nt], ahi[mt], bhi[nt]);
                }
        }
    }

    // Epilogue: fragment c0,c1 = (row, 2tg), (row, 2tg+1); c2,c3 = row+8.
    // Cols 2tg, 2tg+1 are exactly the RoPE even/odd pair.
    #pragma unroll
    for (int mt = 0; mt < 4; mt++) {
        #pragma unroll
        for (int half = 0; half < 2; half++) {
            const int m = bm + wm * 64 + mt * 16 + g + half * 8;
            const int s = m & (S_ - 1);
            #pragma unroll
            for (int nt = 0; nt < 4; nt++) {
                const int n = bn + wn * 32 + nt * 8 + 2 * tg;
                float v0 = acc[mt][nt][half * 2 + 0];
                float v1 = acc[mt][nt][half * 2 + 1];
                if (applyRope) {
                    const int j = (n & (HD_ - 1)) >> 1;
                    float c_  = fc[s * HD_ + j * 2 + 0];
                    float sn_ = fc[s * HD_ + j * 2 + 1];
                    float r0 = v0 * c_  - v1 * sn_;
                    float i0 = v0 * sn_ + v1 * c_;
                    v0 = r0; v1 = i0;
                }
                *(float2*)(C + (size_t)m * D_ + n) = make_float2(v0, v1);
            }
        }
    }
}

// ---------------------------------------------------------------------------
// Flash attention (causal), fp32, 256 threads (8 warps).
// Grid: (S/64, NH, B). ty 0..31 (2 rows each) x tx 0..7 (8 score cols).
// ---------------------------------------------------------------------------
#define QK_STRIDE 129
#define V_STRIDE  132
#define P_STRIDE  65
#define ATT_SMEM_FLOATS (64*QK_STRIDE*2 + 64*V_STRIDE + 64*P_STRIDE)
#define ATT_SMEM_BYTES  (ATT_SMEM_FLOATS * 4)

__global__ __launch_bounds__(256) void attention_kernel(
    const float* __restrict__ Q, const float* __restrict__ K,
    const float* __restrict__ V, float* __restrict__ O)
{
    extern __shared__ float sm[];
    float* Qs = sm;                       // 64 x 129
    float* Ks = Qs + 64*QK_STRIDE;        // 64 x 129
    float* Vs = Ks + 64*QK_STRIDE;        // 64 x 132
    float* Ps = Vs + 64*V_STRIDE;         // 64 x 65

    const int b  = blockIdx.z;
    const int h  = blockIdx.y;
    const int qi = blockIdx.x;
    const int tid = threadIdx.x;
    const int tx = tid & 7;               // 0..7
    const int ty = tid >> 3;              // 0..31 -> 2 rows each

    const size_t base = ((size_t)b * S_ * NH_ + h) * HD_;
    const size_t rowstride = (size_t)NH_ * HD_;   // 2048

    // Load Q tile (64 x 128)
    for (int idx = tid; idx < 64*32; idx += 256) {
        int r  = idx >> 5;
        int c4 = (idx & 31) << 2;
        float4 v = *(const float4*)(Q + base + (size_t)(qi*64 + r) * rowstride + c4);
        Qs[r*QK_STRIDE + c4+0] = v.x; Qs[r*QK_STRIDE + c4+1] = v.y;
        Qs[r*QK_STRIDE + c4+2] = v.z; Qs[r*QK_STRIDE + c4+3] = v.w;
    }

    float m_i[2], l_i[2], o[2][16];
    #pragma unroll
    for (int i = 0; i < 2; i++) {
        m_i[i] = -1e30f; l_i[i] = 0.f;
        #pragma unroll
        for (int c = 0; c < 16; c++) o[i][c] = 0.f;
    }

    const float scale = 0.08838834764831845f;  // 1/sqrt(128)

    for (int kt = 0; kt <= qi; kt++) {
        __syncthreads();   // prior K/V/P fully consumed
        for (int idx = tid; idx < 64*32; idx += 256) {
            int r  = idx >> 5;
            int c4 = (idx & 31) << 2;
            size_t gaddr = base + (size_t)(kt*64 + r) * rowstride + c4;
            float4 vk = *(const float4*)(K + gaddr);
            Ks[r*QK_STRIDE + c4+0] = vk.x; Ks[r*QK_STRIDE + c4+1] = vk.y;
            Ks[r*QK_STRIDE + c4+2] = vk.z; Ks[r*QK_STRIDE + c4+3] = vk.w;
            float4 vv = *(const float4*)(V + gaddr);
            *(float4*)&Vs[r*V_STRIDE + c4] = vv;
        }
        __syncthreads();

        // S = Q K^T (2x8 chunk per thread)
        float sacc[2][8];
        #pragma unroll
        for (int i = 0; i < 2; i++)
            #pragma unroll
            for (int j = 0; j < 8; j++) sacc[i][j] = 0.f;

        #pragma unroll 8
        for (int d = 0; d < HD_; d++) {
            float qv[2], kv[8];
            #pragma unroll
            for (int i = 0; i < 2; i++) qv[i] = Qs[(ty*2 + i)*QK_STRIDE + d];
            #pragma unroll
            for (int j = 0; j < 8; j++) kv[j] = Ks[(tx*8 + j)*QK_STRIDE + d];
            #pragma unroll
            for (int i = 0; i < 2; i++)
                #pragma unroll
                for (int j = 0; j < 8; j++)
                    sacc[i][j] += qv[i] * kv[j];
        }

        const bool diag = (kt == qi);
        #pragma unroll
        for (int i = 0; i < 2; i++) {
            int qrow = qi*64 + ty*2 + i;
            #pragma unroll
            for (int j = 0; j < 8; j++) {
                float sv = sacc[i][j] * scale;
                if (diag && (kt*64 + tx*8 + j) > qrow) sv = -1e30f;
                sacc[i][j] = sv;
            }
            float mloc = sacc[i][0];
            #pragma unroll
            for (int j = 1; j < 8; j++) mloc = fmaxf(mloc, sacc[i][j]);
            mloc = fmaxf(mloc, __shfl_xor_sync(0xffffffffu, mloc, 1));
            mloc = fmaxf(mloc, __shfl_xor_sync(0xffffffffu, mloc, 2));
            mloc = fmaxf(mloc, __shfl_xor_sync(0xffffffffu, mloc, 4));
            float mnew = fmaxf(m_i[i], mloc);
            float corr = __expf(m_i[i] - mnew);
            float lsum = 0.f;
            #pragma unroll
            for (int j = 0; j < 8; j++) {
                float p = __expf(sacc[i][j] - mnew);
                sacc[i][j] = p;
                lsum += p;
            }
            lsum += __shfl_xor_sync(0xffffffffu, lsum, 1);
            lsum += __shfl_xor_sync(0xffffffffu, lsum, 2);
            lsum += __shfl_xor_sync(0xffffffffu, lsum, 4);
            l_i[i] = l_i[i] * corr + lsum;
            m_i[i] = mnew;
            #pragma unroll
            for (int c = 0; c < 16; c++) o[i][c] *= corr;
            #pragma unroll
            for (int j = 0; j < 8; j++)
                Ps[(ty*2 + i)*P_STRIDE + tx*8 + j] = sacc[i][j];
        }
        __syncthreads();

        // O += P V  (rows ty*2.., cols tx*16..)
        #pragma unroll 2
        for (int k = 0; k < 64; k++) {
            float p0 = Ps[(ty*2 + 0)*P_STRIDE + k];
            float p1 = Ps[(ty*2 + 1)*P_STRIDE + k];
            const float* vrow = &Vs[k*V_STRIDE + tx*16];
            #pragma unroll
            for (int c4 = 0; c4 < 4; c4++) {
                float4 v = *(const float4*)(vrow + c4*4);
                o[0][c4*4+0] += p0*v.x; o[0][c4*4+1] += p0*v.y;
                o[0][c4*4+2] += p0*v.z; o[0][c4*4+3] += p0*v.w;
                o[1][c4*4+0] += p1*v.x; o[1][c4*4+1] += p1*v.y;
                o[1][c4*4+2] += p1*v.z; o[1][c4*4+3] += p1*v.w;
            }
        }
    }

    // Normalize and store
    #pragma unroll
    for (int i = 0; i < 2; i++) {
        float inv = 1.0f / l_i[i];
        int srow = qi*64 + ty*2 + i;
        size_t gaddr = base + (size_t)srow * rowstride + tx*16;
        #pragma unroll
        for (int c4 = 0; c4 < 4; c4++) {
            float4 v = make_float4(o[i][c4*4+0]*inv, o[i][c4*4+1]*inv,
                                   o[i][c4*4+2]*inv, o[i][c4*4+3]*inv);
            *(float4*)(O + gaddr + c4*4) = v;
        }
    }
}

// ---------------------------------------------------------------------------
// Launch
// Inputs (metadata order): x, start_pos, freqs_cis, mask, wq, wk, wv, wo
// ---------------------------------------------------------------------------
extern "C" void kernel_launch(void* const* d_in, const int* in_sizes, int n_in,
                              void* d_out, int out_size) {
    (void)in_sizes; (void)n_in; (void)out_size;
    const float* x  = (const float*)d_in[0];
    const float* fc = (const float*)d_in[2];
    const float* wq = (const float*)d_in[4];
    const float* wk = (const float*)d_in[5];
    const float* wv = (const float*)d_in[6];
    const float* wo = (const float*)d_in[7];
    float* out = (float*)d_out;

    float *q, *k, *v, *attn;
    cudaGetSymbolAddress((void**)&q,    g_q);
    cudaGetSymbolAddress((void**)&k,    g_k);
    cudaGetSymbolAddress((void**)&v,    g_v);
    cudaGetSymbolAddress((void**)&attn, g_attn);

    cudaFuncSetAttribute(attention_kernel,
                         cudaFuncAttributeMaxDynamicSharedMemorySize,
                         ATT_SMEM_BYTES);

    dim3 gemm_grid(M_/128, D_/128);   // (32, 16)
    gemm_tf32_rope<<<gemm_grid, 256>>>(x, wq, q, fc, 1);
    gemm_tf32_rope<<<gemm_grid, 256>>>(x, wk, k, fc, 1);
    gemm_tf32_rope<<<gemm_grid, 256>>>(x, wv, v, fc, 0);

    dim3 att_grid(S_/64, NH_, B_);    // (32, 16, 2)
    attention_kernel<<<att_grid, 256, ATT_SMEM_BYTES>>>(q, k, v, attn);

    gemm_tf32_rope<<<gemm_grid, 256>>>(attn, wo, out, fc, 0);
}

// round 5
// speedup vs baseline: 1.3691x; 1.3691x over previous
#include <cuda_runtime.h>
#include <math.h>

// Problem constants
#define B_   2
#define S_   2048
#define D_   2048
#define NH_  16
#define HD_  128
#define M_   (B_*S_)          // 4096 total rows
#define KT_N (D_/8)           // 256 k-tiles (k8) per row
#define NK_  (D_/32)          // 64 k-iterations of BK=32

// ---------------------------------------------------------------------------
// Scratch (static device globals — no runtime allocation allowed)
// ---------------------------------------------------------------------------
__device__ float g_q[(size_t)M_ * D_];
__device__ float g_k[(size_t)M_ * D_];
__device__ float g_v[(size_t)M_ * D_];
__device__ float g_attn[(size_t)M_ * D_];

// Fragment-major pre-split operands (tf32 hi/lo as float bit patterns)
// A-frag: [mtile(16)][ktile(8)] tiles of 128 floats (lane*4 + q)
#define A_FRAG_FLOATS ((size_t)(M_/16) * KT_N * 128)   // 8,388,608
// B-frag: [ntile(8)][ktile(8)] tiles of 64 floats (lane*2 + q)
#define B_FRAG_FLOATS ((size_t)(D_/8) * KT_N * 64)     // 4,194,304
__device__ float g_xah[A_FRAG_FLOATS], g_xal[A_FRAG_FLOATS];
__device__ float g_oah[A_FRAG_FLOATS], g_oal[A_FRAG_FLOATS];
__device__ float g_wbh[4][B_FRAG_FLOATS], g_wbl[4][B_FRAG_FLOATS];

// ---------------------------------------------------------------------------
// tf32 helpers
// ---------------------------------------------------------------------------
__device__ __forceinline__ void split_tf32(float x, float &hi, float &lo) {
    unsigned h, l;
    asm("cvt.rna.tf32.f32 %0, %1;" : "=r"(h) : "f"(x));
    float r = x - __uint_as_float(h);
    asm("cvt.rna.tf32.f32 %0, %1;" : "=r"(l) : "f"(r));
    hi = __uint_as_float(h); lo = __uint_as_float(l);
}

__device__ __forceinline__ void mma_tf32(float* c, const unsigned* a, const unsigned* b) {
    asm volatile(
        "mma.sync.aligned.m16n8k8.row.col.f32.tf32.tf32.f32 "
        "{%0,%1,%2,%3}, {%4,%5,%6,%7}, {%8,%9}, {%0,%1,%2,%3};"
        : "+f"(c[0]), "+f"(c[1]), "+f"(c[2]), "+f"(c[3])
        : "r"(a[0]), "r"(a[1]), "r"(a[2]), "r"(a[3]),
          "r"(b[0]), "r"(b[1]));
}

__device__ __forceinline__ void cp16(unsigned s, const void* g) {
    asm volatile("cp.async.cg.shared.global [%0], [%1], 16;\n" :: "r"(s), "l"(g));
}
__device__ __forceinline__ void cp_commit() {
    asm volatile("cp.async.commit_group;\n" ::: "memory");
}
__device__ __forceinline__ void cp_wait1() {
    asm volatile("cp.async.wait_group 1;\n" ::: "memory");
}

// ---------------------------------------------------------------------------
// Split kernels: natural row-major fp32 -> fragment-major tf32 hi/lo
// ---------------------------------------------------------------------------
// A-operand split. src [R x 2048]. Block region: 64 rows x 32 cols.
// grid (R/64, 64), 256 threads.
__global__ __launch_bounds__(256) void split_a_kernel(
    const float* __restrict__ src, float* __restrict__ dhi, float* __restrict__ dlo)
{
    __shared__ float S[64][33];
    const int tid = threadIdx.x;
    const int row0 = blockIdx.x * 64;
    const int col0 = blockIdx.y * 32;
    #pragma unroll
    for (int i = 0; i < 8; i++) {
        int lin = tid + i * 256;
        int r = lin >> 5, c = lin & 31;
        S[r][c] = src[(size_t)(row0 + r) * D_ + col0 + c];
    }
    __syncthreads();
    const int warp = tid >> 5, lane = tid & 31;
    const int g = lane >> 2, tg = lane & 3;
    #pragma unroll
    for (int s = 0; s < 2; s++) {
        int t  = warp * 2 + s;          // 0..15
        int mt = t >> 2, kt = t & 3;
        float v0 = S[mt*16 + g    ][kt*8 + tg    ];
        float v1 = S[mt*16 + 8 + g][kt*8 + tg    ];
        float v2 = S[mt*16 + g    ][kt*8 + 4 + tg];
        float v3 = S[mt*16 + 8 + g][kt*8 + 4 + tg];
        float4 hi, lo;
        split_tf32(v0, hi.x, lo.x); split_tf32(v1, hi.y, lo.y);
        split_tf32(v2, hi.z, lo.z); split_tf32(v3, hi.w, lo.w);
        size_t base = ((size_t)(blockIdx.x*4 + mt) * KT_N + (blockIdx.y*4 + kt)) * 128 + lane * 4;
        *(float4*)(dhi + base) = hi;
        *(float4*)(dlo + base) = lo;
    }
}

// B-operand split. src W [2048 x 2048] (n rows). Block region: 64 n x 32 k.
// grid (32, 64), 256 threads.
__global__ __launch_bounds__(256) void split_b_kernel(
    const float* __restrict__ src, float* __restrict__ dhi, float* __restrict__ dlo)
{
    __shared__ float S[64][33];
    const int tid = threadIdx.x;
    const int row0 = blockIdx.x * 64;
    const int col0 = blockIdx.y * 32;
    #pragma unroll
    for (int i = 0; i < 8; i++) {
        int lin = tid + i * 256;
        int r = lin >> 5, c = lin & 31;
        S[r][c] = src[(size_t)(row0 + r) * D_ + col0 + c];
    }
    __syncthreads();
    const int warp = tid >> 5, lane = tid & 31;
    const int g = lane >> 2, tg = lane & 3;
    #pragma unroll
    for (int s = 0; s < 4; s++) {
        int t  = warp * 4 + s;          // 0..31
        int nt = t >> 2, kt = t & 3;
        float v0 = S[nt*8 + g][kt*8 + tg    ];
        float v1 = S[nt*8 + g][kt*8 + 4 + tg];
        float2 hi, lo;
        split_tf32(v0, hi.x, lo.x); split_tf32(v1, hi.y, lo.y);
        size_t base = ((size_t)(blockIdx.x*8 + nt) * KT_N + (blockIdx.y*4 + kt)) * 64 + lane * 2;
        *(float2*)(dhi + base) = hi;
        *(float2*)(dlo + base) = lo;
    }
}

// ---------------------------------------------------------------------------
// GEMM (TN) on pre-split fragments, 3xTF32.  C[m,n] = sum_d A[m,d]*W[n,d]
// Block 128x128, BK=32, 256 threads = 8 warps (2m x 4n), warp tile 64x32.
// Double-buffered smem via cp.async. Per buffer (floats):
//   Ahi [0,4096) Alo [4096,8192) Bhi [8192,12288) Blo [12288,16384)
// ---------------------------------------------------------------------------
#define GEMM_SMEM_BYTES (2 * 16384 * 4)   // 131072

__global__ __launch_bounds__(256) void gemm_frag_rope(
    const float* __restrict__ Ahi, const float* __restrict__ Alo,
    const float* __restrict__ Bhi, const float* __restrict__ Blo,
    float* __restrict__ C, const float* __restrict__ fc, int applyRope)
{
    extern __shared__ float smf[];
    const int tid  = threadIdx.x;
    const int warp = tid >> 5, lane = tid & 31;
    const int wm = warp >> 2, wn = warp & 3;
    const int g  = lane >> 2, tg = lane & 3;
    const int MT0 = blockIdx.x * 8;    // 8 mtiles per block
    const int NT0 = blockIdx.y * 16;   // 16 ntiles per block

    float acc[4][4][4];
    #pragma unroll
    for (int i = 0; i < 4; i++)
        #pragma unroll
        for (int j = 0; j < 4; j++)
            #pragma unroll
            for (int f = 0; f < 4; f++) acc[i][j][f] = 0.f;

    unsigned sbase = (unsigned)__cvta_generic_to_shared(smf);

    // issue async copy of k-iteration kt into buffer b
    auto copy_tile = [&](int kt, int b) {
        unsigned soff = sbase + b * 16384u * 4u;
        // A: 32 tiles of 128 floats; 1024 float4 -> 4 per thread
        #pragma unroll
        for (int i = 0; i < 4; i++) {
            int id = tid + i * 256;
            int tile = id >> 5, pos = id & 31;       // tile = mtl*4+ktl
            size_t gb = ((size_t)(MT0 + (tile >> 2)) * KT_N + kt*4 + (tile & 3)) * 128 + pos * 4;
            unsigned so = soff + (unsigned)(tile * 128 + pos * 4) * 4u;
            cp16(so,               Ahi + gb);
            cp16(so + 4096u * 4u,  Alo + gb);
        }
        // B: 64 tiles of 64 floats; 1024 float4 -> 4 per thread
        #pragma unroll
        for (int i = 0; i < 4; i++) {
            int id = tid + i * 256;
            int tile = id >> 4, pos = id & 15;       // tile = ntl*4+ktl
            size_t gb = ((size_t)(NT0 + (tile >> 2)) * KT_N + kt*4 + (tile & 3)) * 64 + pos * 4;
            unsigned so = soff + (unsigned)(8192 + tile * 64 + pos * 4) * 4u;
            cp16(so,               Bhi + gb);
            cp16(so + 4096u * 4u,  Blo + gb);
        }
    };

    copy_tile(0, 0);
    cp_commit();

    for (int kt = 0; kt < NK_; kt++) {
        if (kt + 1 < NK_) copy_tile(kt + 1, (kt + 1) & 1);
        cp_commit();
        cp_wait1();
        __syncthreads();

        const float* buf = smf + (kt & 1) * 16384;
        const uint4* As_h = (const uint4*)(buf);
        const uint4* As_l = (const uint4*)(buf + 4096);
        const uint2* Bs_h = (const uint2*)(buf + 8192);
        const uint2* Bs_l = (const uint2*)(buf + 12288);

        #pragma unroll
        for (int ks = 0; ks < 4; ks++) {
            uint4 ah[4], al[4];
            #pragma unroll
            for (int mt = 0; mt < 4; mt++) {
                int idx = ((wm*4 + mt)*4 + ks) * 32 + lane;
                ah[mt] = As_h[idx];
                al[mt] = As_l[idx];
            }
            uint2 bh[4], bl[4];
            #pragma unroll
            for (int nt = 0; nt < 4; nt++) {
                int idx = ((wn*4 + nt)*4 + ks) * 32 + lane;
                bh[nt] = Bs_h[idx];
                bl[nt] = Bs_l[idx];
            }
            #pragma unroll
            for (int mt = 0; mt < 4; mt++)
                #pragma unroll
                for (int nt = 0; nt < 4; nt++) {
                    mma_tf32(acc[mt][nt], (const unsigned*)&ah[mt], (const unsigned*)&bl[nt]);
                    mma_tf32(acc[mt][nt], (const unsigned*)&al[mt], (const unsigned*)&bh[nt]);
                    mma_tf32(acc[mt][nt], (const unsigned*)&ah[mt], (const unsigned*)&bh[nt]);
                }
        }
        __syncthreads();
    }

    // Epilogue (validated in R4): c0,c1=(row,2tg),(row,2tg+1); c2,c3=row+8.
    const int bm = blockIdx.x * 128, bn = blockIdx.y * 128;
    #pragma unroll
    for (int mt = 0; mt < 4; mt++) {
        #pragma unroll
        for (int half = 0; half < 2; half++) {
            const int m = bm + wm * 64 + mt * 16 + g + half * 8;
            const int s = m & (S_ - 1);
            #pragma unroll
            for (int nt = 0; nt < 4; nt++) {
                const int n = bn + wn * 32 + nt * 8 + 2 * tg;
                float v0 = acc[mt][nt][half * 2 + 0];
                float v1 = acc[mt][nt][half * 2 + 1];
                if (applyRope) {
                    const int j = (n & (HD_ - 1)) >> 1;
                    float c_  = fc[s * HD_ + j * 2 + 0];
                    float sn_ = fc[s * HD_ + j * 2 + 1];
                    float r0 = v0 * c_  - v1 * sn_;
                    float i0 = v0 * sn_ + v1 * c_;
                    v0 = r0; v1 = i0;
                }
                *(float2*)(C + (size_t)m * D_ + n) = make_float2(v0, v1);
            }
        }
    }
}

// ---------------------------------------------------------------------------
// Flash attention (causal), fp32 — R2 version (measured best), verbatim.
// Grid: (S/64, NH, B). 128 threads = (ty 0..15 rows-of-4) x (tx 0..7 cols-of-8).
// ---------------------------------------------------------------------------
#define QK_STRIDE 129
#define V_STRIDE  132
#define P_STRIDE  65
#define ATT_SMEM_FLOATS (64*QK_STRIDE*2 + 64*V_STRIDE + 64*P_STRIDE)
#define ATT_SMEM_BYTES  (ATT_SMEM_FLOATS * 4)

__global__ __launch_bounds__(128) void attention_kernel(
    const float* __restrict__ Q, const float* __restrict__ K,
    const float* __restrict__ V, float* __restrict__ O)
{
    extern __shared__ float sm[];
    float* Qs = sm;
    float* Ks = Qs + 64*QK_STRIDE;
    float* Vs = Ks + 64*QK_STRIDE;
    float* Ps = Vs + 64*V_STRIDE;

    const int b  = blockIdx.z;
    const int h  = blockIdx.y;
    const int qi = blockIdx.x;
    const int tid = threadIdx.x;
    const int tx = tid & 7;
    const int ty = tid >> 3;

    const size_t base = ((size_t)b * S_ * NH_ + h) * HD_;
    const size_t rowstride = (size_t)NH_ * HD_;

    for (int idx = tid; idx < 64*32; idx += 128) {
        int r  = idx >> 5;
        int c4 = (idx & 31) << 2;
        float4 v = *(const float4*)(Q + base + (size_t)(qi*64 + r) * rowstride + c4);
        Qs[r*QK_STRIDE + c4+0] = v.x; Qs[r*QK_STRIDE + c4+1] = v.y;
        Qs[r*QK_STRIDE + c4+2] = v.z; Qs[r*QK_STRIDE + c4+3] = v.w;
    }

    float m_i[4], l_i[4], o[4][16];
    #pragma unroll
    for (int i = 0; i < 4; i++) {
        m_i[i] = -1e30f; l_i[i] = 0.f;
        #pragma unroll
        for (int c = 0; c < 16; c++) o[i][c] = 0.f;
    }

    const float scale = 0.08838834764831845f;

    for (int kt = 0; kt <= qi; kt++) {
        __syncthreads();
        for (int idx = tid; idx < 64*32; idx += 128) {
            int r  = idx >> 5;
            int c4 = (idx & 31) << 2;
            size_t ga = base + (size_t)(kt*64 + r) * rowstride + c4;
            float4 vk = *(const float4*)(K + ga);
            Ks[r*QK_STRIDE + c4+0] = vk.x; Ks[r*QK_STRIDE + c4+1] = vk.y;
            Ks[r*QK_STRIDE + c4+2] = vk.z; Ks[r*QK_STRIDE + c4+3] = vk.w;
            float4 vv = *(const float4*)(V + ga);
            *(float4*)&Vs[r*V_STRIDE + c4] = vv;
        }
        __syncthreads();

        float sacc[4][8];
        #pragma unroll
        for (int i = 0; i < 4; i++)
            #pragma unroll
            for (int j = 0; j < 8; j++) sacc[i][j] = 0.f;

        #pragma unroll 8
        for (int d = 0; d < HD_; d++) {
            float qv[4], kv[8];
            #pragma unroll
            for (int i = 0; i < 4; i++) qv[i] = Qs[(ty*4 + i)*QK_STRIDE + d];
            #pragma unroll
            for (int j = 0; j < 8; j++) kv[j] = Ks[(tx*8 + j)*QK_STRIDE + d];
            #pragma unroll
            for (int i = 0; i < 4; i++)
                #pragma unroll
                for (int j = 0; j < 8; j++)
                    sacc[i][j] += qv[i] * kv[j];
        }

        const bool diag = (kt == qi);
        #pragma unroll
        for (int i = 0; i < 4; i++) {
            int qrow = qi*64 + ty*4 + i;
            #pragma unroll
            for (int j = 0; j < 8; j++) {
                float sv = sacc[i][j] * scale;
                if (diag && (kt*64 + tx*8 + j) > qrow) sv = -1e30f;
                sacc[i][j] = sv;
            }
            float mloc = sacc[i][0];
            #pragma unroll
            for (int j = 1; j < 8; j++) mloc = fmaxf(mloc, sacc[i][j]);
            mloc = fmaxf(mloc, __shfl_xor_sync(0xffffffffu, mloc, 1));
            mloc = fmaxf(mloc, __shfl_xor_sync(0xffffffffu, mloc, 2));
            mloc = fmaxf(mloc, __shfl_xor_sync(0xffffffffu, mloc, 4));
            float mnew = fmaxf(m_i[i], mloc);
            float corr = __expf(m_i[i] - mnew);
            float lsum = 0.f;
            #pragma unroll
            for (int j = 0; j < 8; j++) {
                float p = __expf(sacc[i][j] - mnew);
                sacc[i][j] = p;
                lsum += p;
            }
            lsum += __shfl_xor_sync(0xffffffffu, lsum, 1);
            lsum += __shfl_xor_sync(0xffffffffu, lsum, 2);
            lsum += __shfl_xor_sync(0xffffffffu, lsum, 4);
            l_i[i] = l_i[i] * corr + lsum;
            m_i[i] = mnew;
            #pragma unroll
            for (int c = 0; c < 16; c++) o[i][c] *= corr;
            #pragma unroll
            for (int j = 0; j < 8; j++)
                Ps[(ty*4 + i)*P_STRIDE + tx*8 + j] = sacc[i][j];
        }
        __syncthreads();

        #pragma unroll 2
        for (int k = 0; k < 64; k++) {
            float p0 = Ps[(ty*4 + 0)*P_STRIDE + k];
            float p1 = Ps[(ty*4 + 1)*P_STRIDE + k];
            float p2 = Ps[(ty*4 + 2)*P_STRIDE + k];
            float p3 = Ps[(ty*4 + 3)*P_STRIDE + k];
            const float* vrow = &Vs[k*V_STRIDE + tx*16];
            #pragma unroll
            for (int c4 = 0; c4 < 4; c4++) {
                float4 v = *(const float4*)(vrow + c4*4);
                o[0][c4*4+0] += p0*v.x; o[0][c4*4+1] += p0*v.y;
                o[0][c4*4+2] += p0*v.z; o[0][c4*4+3] += p0*v.w;
                o[1][c4*4+0] += p1*v.x; o[1][c4*4+1] += p1*v.y;
                o[1][c4*4+2] += p1*v.z; o[1][c4*4+3] += p1*v.w;
                o[2][c4*4+0] += p2*v.x; o[2][c4*4+1] += p2*v.y;
                o[2][c4*4+2] += p2*v.z; o[2][c4*4+3] += p2*v.w;
                o[3][c4*4+0] += p3*v.x; o[3][c4*4+1] += p3*v.y;
                o[3][c4*4+2] += p3*v.z; o[3][c4*4+3] += p3*v.w;
            }
        }
    }

    #pragma unroll
    for (int i = 0; i < 4; i++) {
        float inv = 1.0f / l_i[i];
        int srow = qi*64 + ty*4 + i;
        size_t ga = base + (size_t)srow * rowstride + tx*16;
        #pragma unroll
        for (int c4 = 0; c4 < 4; c4++) {
            float4 v = make_float4(o[i][c4*4+0]*inv, o[i][c4*4+1]*inv,
                                   o[i][c4*4+2]*inv, o[i][c4*4+3]*inv);
            *(float4*)(O + ga + c4*4) = v;
        }
    }
}

// ---------------------------------------------------------------------------
// Launch. Inputs: x, start_pos, freqs_cis, mask, wq, wk, wv, wo
// ---------------------------------------------------------------------------
extern "C" void kernel_launch(void* const* d_in, const int* in_sizes, int n_in,
                              void* d_out, int out_size) {
    (void)in_sizes; (void)n_in; (void)out_size;
    const float* x  = (const float*)d_in[0];
    const float* fc = (const float*)d_in[2];
    const float* w[4] = { (const float*)d_in[4], (const float*)d_in[5],
                          (const float*)d_in[6], (const float*)d_in[7] };
    float* out = (float*)d_out;

    float *q, *k, *v, *attn, *xah, *xal, *oah, *oal, *wbh, *wbl;
    cudaGetSymbolAddress((void**)&q,    g_q);
    cudaGetSymbolAddress((void**)&k,    g_k);
    cudaGetSymbolAddress((void**)&v,    g_v);
    cudaGetSymbolAddress((void**)&attn, g_attn);
    cudaGetSymbolAddress((void**)&xah,  g_xah);
    cudaGetSymbolAddress((void**)&xal,  g_xal);
    cudaGetSymbolAddress((void**)&oah,  g_oah);
    cudaGetSymbolAddress((void**)&oal,  g_oal);
    cudaGetSymbolAddress((void**)&wbh,  g_wbh);
    cudaGetSymbolAddress((void**)&wbl,  g_wbl);

    cudaFuncSetAttribute(attention_kernel,
                         cudaFuncAttributeMaxDynamicSharedMemorySize, ATT_SMEM_BYTES);
    cudaFuncSetAttribute(gemm_frag_rope,
                         cudaFuncAttributeMaxDynamicSharedMemorySize, GEMM_SMEM_BYTES);

    // Pre-split operands into fragment-major tf32 hi/lo
    split_a_kernel<<<dim3(M_/64, D_/32), 256>>>(x, xah, xal);
    for (int i = 0; i < 4; i++)
        split_b_kernel<<<dim3(D_/64, D_/32), 256>>>(w[i],
            wbh + (size_t)i * B_FRAG_FLOATS, wbl + (size_t)i * B_FRAG_FLOATS);

    dim3 gemm_grid(M_/128, D_/128);   // (32, 16)
    gemm_frag_rope<<<gemm_grid, 256, GEMM_SMEM_BYTES>>>(xah, xal,
        wbh + 0*B_FRAG_FLOATS, wbl + 0*B_FRAG_FLOATS, q, fc, 1);
    gemm_frag_rope<<<gemm_grid, 256, GEMM_SMEM_BYTES>>>(xah, xal,
        wbh + 1*B_FRAG_FLOATS, wbl + 1*B_FRAG_FLOATS, k, fc, 1);
    gemm_frag_rope<<<gemm_grid, 256, GEMM_SMEM_BYTES>>>(xah, xal,
        wbh + 2*B_FRAG_FLOATS, wbl + 2*B_FRAG_FLOATS, v, fc, 0);

    dim3 att_grid(S_/64, NH_, B_);    // (32, 16, 2)
    attention_kernel<<<att_grid, 128, ATT_SMEM_BYTES>>>(q, k, v, attn);

    split_a_kernel<<<dim3(M_/64, D_/32), 256>>>(attn, oah, oal);
    gemm_frag_rope<<<gemm_grid, 256, GEMM_SMEM_BYTES>>>(oah, oal,
        wbh + 3*B_FRAG_FLOATS, wbl + 3*B_FRAG_FLOATS, out, fc, 0);
}

// round 6
// speedup vs baseline: 2.0031x; 1.4630x over previous
#include <cuda_runtime.h>
#include <math.h>

// Problem constants
#define B_   2
#define S_   2048
#define D_   2048
#define NH_  16
#define HD_  128
#define M_   (B_*S_)          // 4096 total rows
#define KT_N (D_/8)           // 256 k-tiles (k8) per row
#define NK_  (D_/32)          // 64 k-iterations of BK=32

// ---------------------------------------------------------------------------
// Scratch (static device globals — no runtime allocation allowed)
// ---------------------------------------------------------------------------
__device__ float g_q[(size_t)M_ * D_];
__device__ float g_k[(size_t)M_ * D_];
__device__ float g_v[(size_t)M_ * D_];
__device__ float g_attn[(size_t)M_ * D_];

// Fragment-major pre-split operands (tf32 hi/lo as float bit patterns)
#define A_FRAG_FLOATS ((size_t)(M_/16) * KT_N * 128)   // 8,388,608
#define B_FRAG_FLOATS ((size_t)(D_/8) * KT_N * 64)     // 4,194,304
__device__ float g_xah[A_FRAG_FLOATS], g_xal[A_FRAG_FLOATS];
__device__ float g_oah[A_FRAG_FLOATS], g_oal[A_FRAG_FLOATS];
__device__ float g_wbh[4][B_FRAG_FLOATS], g_wbl[4][B_FRAG_FLOATS];

// Attention fragment arrays, per (b,h):
// Q A-frag:  [bh 32][mt 128][kthd 16][128]
// K B-frag:  [bh 32][nt 256][kthd 16][64]
// V B-frag(T): [bh 32][nthd 16][kts 256][64]
#define QF_FLOATS ((size_t)32 * 128 * 16 * 128)
#define KF_FLOATS ((size_t)32 * 256 * 16 * 64)
#define VF_FLOATS ((size_t)32 * 16 * 256 * 64)
__device__ float g_qfh[QF_FLOATS], g_qfl[QF_FLOATS];
__device__ float g_kfh[KF_FLOATS], g_kfl[KF_FLOATS];
__device__ float g_vfh[VF_FLOATS], g_vfl[VF_FLOATS];

// ---------------------------------------------------------------------------
// tf32 helpers
// ---------------------------------------------------------------------------
__device__ __forceinline__ void split_tf32(float x, float &hi, float &lo) {
    unsigned h, l;
    asm("cvt.rna.tf32.f32 %0, %1;" : "=r"(h) : "f"(x));
    float r = x - __uint_as_float(h);
    asm("cvt.rna.tf32.f32 %0, %1;" : "=r"(l) : "f"(r));
    hi = __uint_as_float(h); lo = __uint_as_float(l);
}

__device__ __forceinline__ void mma_tf32(float* c, const unsigned* a, const unsigned* b) {
    asm volatile(
        "mma.sync.aligned.m16n8k8.row.col.f32.tf32.tf32.f32 "
        "{%0,%1,%2,%3}, {%4,%5,%6,%7}, {%8,%9}, {%0,%1,%2,%3};"
        : "+f"(c[0]), "+f"(c[1]), "+f"(c[2]), "+f"(c[3])
        : "r"(a[0]), "r"(a[1]), "r"(a[2]), "r"(a[3]),
          "r"(b[0]), "r"(b[1]));
}
__device__ __forceinline__ void mma42(float* c, const uint4& a, const uint2& b) {
    asm volatile(
        "mma.sync.aligned.m16n8k8.row.col.f32.tf32.tf32.f32 "
        "{%0,%1,%2,%3}, {%4,%5,%6,%7}, {%8,%9}, {%0,%1,%2,%3};"
        : "+f"(c[0]), "+f"(c[1]), "+f"(c[2]), "+f"(c[3])
        : "r"(a.x), "r"(a.y), "r"(a.z), "r"(a.w), "r"(b.x), "r"(b.y));
}

__device__ __forceinline__ void cp16(unsigned s, const void* g) {
    asm volatile("cp.async.cg.shared.global [%0], [%1], 16;\n" :: "r"(s), "l"(g));
}
__device__ __forceinline__ void cp_commit() {
    asm volatile("cp.async.commit_group;\n" ::: "memory");
}
__device__ __forceinline__ void cp_wait1() {
    asm volatile("cp.async.wait_group 1;\n" ::: "memory");
}

// ---------------------------------------------------------------------------
// Split kernels (row-major fp32 -> fragment-major tf32 hi/lo)
// ---------------------------------------------------------------------------
// A-operand split (GEMM activations). grid (R/64, 64), 256 threads.
__global__ __launch_bounds__(256) void split_a_kernel(
    const float* __restrict__ src, float* __restrict__ dhi, float* __restrict__ dlo)
{
    __shared__ float S[64][33];
    const int tid = threadIdx.x;
    const int row0 = blockIdx.x * 64;
    const int col0 = blockIdx.y * 32;
    #pragma unroll
    for (int i = 0; i < 8; i++) {
        int lin = tid + i * 256;
        int r = lin >> 5, c = lin & 31;
        S[r][c] = src[(size_t)(row0 + r) * D_ + col0 + c];
    }
    __syncthreads();
    const int warp = tid >> 5, lane = tid & 31;
    const int g = lane >> 2, tg = lane & 3;
    #pragma unroll
    for (int s = 0; s < 2; s++) {
        int t  = warp * 2 + s;
        int mt = t >> 2, kt = t & 3;
        float4 hi, lo;
        split_tf32(S[mt*16 + g    ][kt*8 + tg    ], hi.x, lo.x);
        split_tf32(S[mt*16 + 8 + g][kt*8 + tg    ], hi.y, lo.y);
        split_tf32(S[mt*16 + g    ][kt*8 + 4 + tg], hi.z, lo.z);
        split_tf32(S[mt*16 + 8 + g][kt*8 + 4 + tg], hi.w, lo.w);
        size_t base = ((size_t)(blockIdx.x*4 + mt) * KT_N + (blockIdx.y*4 + kt)) * 128 + lane * 4;
        *(float4*)(dhi + base) = hi;
        *(float4*)(dlo + base) = lo;
    }
}

// B-operand split (weights). grid (32, 64), 256 threads.
__global__ __launch_bounds__(256) void split_b_kernel(
    const float* __restrict__ src, float* __restrict__ dhi, float* __restrict__ dlo)
{
    __shared__ float S[64][33];
    const int tid = threadIdx.x;
    const int row0 = blockIdx.x * 64;
    const int col0 = blockIdx.y * 32;
    #pragma unroll
    for (int i = 0; i < 8; i++) {
        int lin = tid + i * 256;
        int r = lin >> 5, c = lin & 31;
        S[r][c] = src[(size_t)(row0 + r) * D_ + col0 + c];
    }
    __syncthreads();
    const int warp = tid >> 5, lane = tid & 31;
    const int g = lane >> 2, tg = lane & 3;
    #pragma unroll
    for (int s = 0; s < 4; s++) {
        int t  = warp * 4 + s;
        int nt = t >> 2, kt = t & 3;
        float2 hi, lo;
        split_tf32(S[nt*8 + g][kt*8 + tg    ], hi.x, lo.x);
        split_tf32(S[nt*8 + g][kt*8 + 4 + tg], hi.y, lo.y);
        size_t base = ((size_t)(blockIdx.x*8 + nt) * KT_N + (blockIdx.y*4 + kt)) * 64 + lane * 2;
        *(float2*)(dhi + base) = hi;
        *(float2*)(dlo + base) = lo;
    }
}

// --- per-(b,h) splits for attention. grid (32 sb, 4 db, 32 bh), 256 thr. ---
__global__ __launch_bounds__(256) void split_q_frag(
    const float* __restrict__ src, float* __restrict__ dhi, float* __restrict__ dlo)
{
    __shared__ float S[64][33];
    const int tid = threadIdx.x;
    const int bh = blockIdx.z;
    const int b = bh >> 4, h = bh & 15;
    const int row0 = b * S_ + blockIdx.x * 64;
    const int col0 = h * HD_ + blockIdx.y * 32;
    #pragma unroll
    for (int i = 0; i < 8; i++) {
        int lin = tid + i * 256;
        int r = lin >> 5, c = lin & 31;
        S[r][c] = src[(size_t)(row0 + r) * D_ + col0 + c];
    }
    __syncthreads();
    const int warp = tid >> 5, lane = tid & 31;
    const int g = lane >> 2, tg = lane & 3;
    #pragma unroll
    for (int s = 0; s < 2; s++) {
        int t  = warp * 2 + s;
        int mt = t >> 2, kt = t & 3;
        float4 hi, lo;
        split_tf32(S[mt*16 + g    ][kt*8 + tg    ], hi.x, lo.x);
        split_tf32(S[mt*16 + 8 + g][kt*8 + tg    ], hi.y, lo.y);
        split_tf32(S[mt*16 + g    ][kt*8 + 4 + tg], hi.z, lo.z);
        split_tf32(S[mt*16 + 8 + g][kt*8 + 4 + tg], hi.w, lo.w);
        size_t base = (((size_t)bh*128 + blockIdx.x*4 + mt) * 16 + (blockIdx.y*4 + kt)) * 128 + lane * 4;
        *(float4*)(dhi + base) = hi;
        *(float4*)(dlo + base) = lo;
    }
}

__global__ __launch_bounds__(256) void split_k_frag(
    const float* __restrict__ src, float* __restrict__ dhi, float* __restrict__ dlo)
{
    __shared__ float S[64][33];
    const int tid = threadIdx.x;
    const int bh = blockIdx.z;
    const int b = bh >> 4, h = bh & 15;
    const int row0 = b * S_ + blockIdx.x * 64;
    const int col0 = h * HD_ + blockIdx.y * 32;
    #pragma unroll
    for (int i = 0; i < 8; i++) {
        int lin = tid + i * 256;
        int r = lin >> 5, c = lin & 31;
        S[r][c] = src[(size_t)(row0 + r) * D_ + col0 + c];
    }
    __syncthreads();
    const int warp = tid >> 5, lane = tid & 31;
    const int g = lane >> 2, tg = lane & 3;
    #pragma unroll
    for (int s = 0; s < 4; s++) {
        int t  = warp * 4 + s;
        int nt = t >> 2, kt = t & 3;
        float2 hi, lo;
        split_tf32(S[nt*8 + g][kt*8 + tg    ], hi.x, lo.x);
        split_tf32(S[nt*8 + g][kt*8 + 4 + tg], hi.y, lo.y);
        size_t base = (((size_t)bh*256 + blockIdx.x*8 + nt) * 16 + (blockIdx.y*4 + kt)) * 64 + lane * 2;
        *(float2*)(dhi + base) = hi;
        *(float2*)(dlo + base) = lo;
    }
}

// V transposed split: B-frag with n = headdim, k = seqpos.
__global__ __launch_bounds__(256) void split_v_frag(
    const float* __restrict__ src, float* __restrict__ dhi, float* __restrict__ dlo)
{
    __shared__ float S[64][33];
    const int tid = threadIdx.x;
    const int bh = blockIdx.z;
    const int b = bh >> 4, h = bh & 15;
    const int row0 = b * S_ + blockIdx.x * 64;   // seq
    const int col0 = h * HD_ + blockIdx.y * 32;  // headdim
    #pragma unroll
    for (int i = 0; i < 8; i++) {
        int lin = tid + i * 256;
        int r = lin >> 5, c = lin & 31;
        S[r][c] = src[(size_t)(row0 + r) * D_ + col0 + c];
    }
    __syncthreads();
    const int warp = tid >> 5, lane = tid & 31;
    const int g = lane >> 2, tg = lane & 3;
    // 32 (ntl over d: 4, ktl over s: 8) pairs; frag element: b0 = V[s=ktl*8+tg][d=ntl*8+g]
    #pragma unroll
    for (int s = 0; s < 4; s++) {
        int t   = warp * 4 + s;
        int ntl = t & 3, ktl = t >> 2;
        float2 hi, lo;
        split_tf32(S[ktl*8 + tg    ][ntl*8 + g], hi.x, lo.x);
        split_tf32(S[ktl*8 + 4 + tg][ntl*8 + g], hi.y, lo.y);
        size_t base = (((size_t)bh*16 + blockIdx.y*4 + ntl) * 256 + (blockIdx.x*8 + ktl)) * 64 + lane * 2;
        *(float2*)(dhi + base) = hi;
        *(float2*)(dlo + base) = lo;
    }
}

// ---------------------------------------------------------------------------
// GEMM (TN) on pre-split fragments, 3xTF32 (validated R5).
// ---------------------------------------------------------------------------
#define GEMM_SMEM_BYTES (2 * 16384 * 4)   // 131072

__global__ __launch_bounds__(256) void gemm_frag_rope(
    const float* __restrict__ Ahi, const float* __restrict__ Alo,
    const float* __restrict__ Bhi, const float* __restrict__ Blo,
    float* __restrict__ C, const float* __restrict__ fc, int applyRope)
{
    extern __shared__ float smf[];
    const int tid  = threadIdx.x;
    const int warp = tid >> 5, lane = tid & 31;
    const int wm = warp >> 2, wn = warp & 3;
    const int g  = lane >> 2, tg = lane & 3;
    const int MT0 = blockIdx.x * 8;
    const int NT0 = blockIdx.y * 16;

    float acc[4][4][4];
    #pragma unroll
    for (int i = 0; i < 4; i++)
        #pragma unroll
        for (int j = 0; j < 4; j++)
            #pragma unroll
            for (int f = 0; f < 4; f++) acc[i][j][f] = 0.f;

    unsigned sbase = (unsigned)__cvta_generic_to_shared(smf);

    auto copy_tile = [&](int kt, int b) {
        unsigned soff = sbase + b * 16384u * 4u;
        #pragma unroll
        for (int i = 0; i < 4; i++) {
            int id = tid + i * 256;
            int tile = id >> 5, pos = id & 31;
            size_t gb = ((size_t)(MT0 + (tile >> 2)) * KT_N + kt*4 + (tile & 3)) * 128 + pos * 4;
            unsigned so = soff + (unsigned)(tile * 128 + pos * 4) * 4u;
            cp16(so,               Ahi + gb);
            cp16(so + 4096u * 4u,  Alo + gb);
        }
        #pragma unroll
        for (int i = 0; i < 4; i++) {
            int id = tid + i * 256;
            int tile = id >> 4, pos = id & 15;
            size_t gb = ((size_t)(NT0 + (tile >> 2)) * KT_N + kt*4 + (tile & 3)) * 64 + pos * 4;
            unsigned so = soff + (unsigned)(8192 + tile * 64 + pos * 4) * 4u;
            cp16(so,               Bhi + gb);
            cp16(so + 4096u * 4u,  Blo + gb);
        }
    };

    copy_tile(0, 0);
    cp_commit();

    for (int kt = 0; kt < NK_; kt++) {
        if (kt + 1 < NK_) copy_tile(kt + 1, (kt + 1) & 1);
        cp_commit();
        cp_wait1();
        __syncthreads();

        const float* buf = smf + (kt & 1) * 16384;
        const uint4* As_h = (const uint4*)(buf);
        const uint4* As_l = (const uint4*)(buf + 4096);
        const uint2* Bs_h = (const uint2*)(buf + 8192);
        const uint2* Bs_l = (const uint2*)(buf + 12288);

        #pragma unroll
        for (int ks = 0; ks < 4; ks++) {
            uint4 ah[4], al[4];
            #pragma unroll
            for (int mt = 0; mt < 4; mt++) {
                int idx = ((wm*4 + mt)*4 + ks) * 32 + lane;
                ah[mt] = As_h[idx];
                al[mt] = As_l[idx];
            }
            uint2 bh[4], bl[4];
            #pragma unroll
            for (int nt = 0; nt < 4; nt++) {
                int idx = ((wn*4 + nt)*4 + ks) * 32 + lane;
                bh[nt] = Bs_h[idx];
                bl[nt] = Bs_l[idx];
            }
            #pragma unroll
            for (int mt = 0; mt < 4; mt++)
                #pragma unroll
                for (int nt = 0; nt < 4; nt++) {
                    mma_tf32(acc[mt][nt], (const unsigned*)&ah[mt], (const unsigned*)&bl[nt]);
                    mma_tf32(acc[mt][nt], (const unsigned*)&al[mt], (const unsigned*)&bh[nt]);
                    mma_tf32(acc[mt][nt], (const unsigned*)&ah[mt], (const unsigned*)&bh[nt]);
                }
        }
        __syncthreads();
    }

    const int bm = blockIdx.x * 128, bn = blockIdx.y * 128;
    #pragma unroll
    for (int mt = 0; mt < 4; mt++) {
        #pragma unroll
        for (int half = 0; half < 2; half++) {
            const int m = bm + wm * 64 + mt * 16 + g + half * 8;
            const int s = m & (S_ - 1);
            #pragma unroll
            for (int nt = 0; nt < 4; nt++) {
                const int n = bn + wn * 32 + nt * 8 + 2 * tg;
                float v0 = acc[mt][nt][half * 2 + 0];
                float v1 = acc[mt][nt][half * 2 + 1];
                if (applyRope) {
                    const int j = (n & (HD_ - 1)) >> 1;
                    float c_  = fc[s * HD_ + j * 2 + 0];
                    float sn_ = fc[s * HD_ + j * 2 + 1];
                    float r0 = v0 * c_  - v1 * sn_;
                    float i0 = v0 * sn_ + v1 * c_;
                    v0 = r0; v1 = i0;
                }
                *(float2*)(C + (size_t)m * D_ + n) = make_float2(v0, v1);
            }
        }
    }
}

// ---------------------------------------------------------------------------
// Tensor-core flash attention (causal, 3xTF32).
// Grid (S/64, NH, B), 128 threads = 4 warps; warp w owns q rows [w*16, w*16+16).
// kv-tile = 32, double-buffered via cp.async.
// smem floats: Qh 8192 | Ql 8192 | KV 2x16384 | Ps 64x35 float2 (4480 floats)
// ---------------------------------------------------------------------------
#define ATT2_SMEM_FLOATS (8192 + 8192 + 32768 + 64*35*2)
#define ATT2_SMEM_BYTES  (ATT2_SMEM_FLOATS * 4)

__global__ __launch_bounds__(128) void attention_mma(
    const float* __restrict__ Qh_, const float* __restrict__ Ql_,
    const float* __restrict__ Kh_, const float* __restrict__ Kl_,
    const float* __restrict__ Vh_, const float* __restrict__ Vl_,
    float* __restrict__ O)
{
    extern __shared__ float sm[];
    float* Qh = sm;               // [mt 4][ks 16][128]
    float* Ql = Qh + 8192;
    float* KV = Ql + 8192;        // 2 x { Kh 4096 | Kl 4096 | Vh 4096 | Vl 4096 }
    float2* Ps2 = (float2*)(KV + 32768);   // [64][35] (hi,lo)

    const int tid  = threadIdx.x;
    const int warp = tid >> 5, lane = tid & 31;
    const int g = lane >> 2, tg = lane & 3;
    const int qi = blockIdx.x;
    const int bh = blockIdx.z * NH_ + blockIdx.y;
    const int Q0 = qi * 64;
    const float scale = 0.08838834764831845f;   // 1/sqrt(128)

    // Load Q tile fragments (contiguous 8192 floats per array)
    {
        size_t qbase = ((size_t)bh * 128 + qi * 4) * 2048;
        const float4* srch = (const float4*)(Qh_ + qbase);
        const float4* srcl = (const float4*)(Ql_ + qbase);
        for (int i = tid; i < 2048; i += 128) {
            ((float4*)Qh)[i] = srch[i];
            ((float4*)Ql)[i] = srcl[i];
        }
    }

    unsigned kvbase = (unsigned)__cvta_generic_to_shared(KV);

    auto copy_kv = [&](int kt, int b) {
        unsigned soff = kvbase + (unsigned)b * 16384u * 4u;
        size_t kbase = ((size_t)bh * 256 + kt * 4) * 1024;
        for (int i = tid; i < 1024; i += 128) {
            cp16(soff + i * 16u,                Kh_ + kbase + i * 4);
            cp16(soff + 4096u*4u + i * 16u,     Kl_ + kbase + i * 4);
        }
        for (int i = tid; i < 1024; i += 128) {
            int nt = i >> 6, pos = i & 63;
            size_t vb = (((size_t)bh * 16 + nt) * 256 + (size_t)kt * 4) * 64 + pos * 4;
            cp16(soff + 8192u*4u  + i * 16u,    Vh_ + vb);
            cp16(soff + 12288u*4u + i * 16u,    Vl_ + vb);
        }
    };

    float m0 = -1e30f, m1 = -1e30f, l0 = 0.f, l1 = 0.f;
    float o[16][4];
    #pragma unroll
    for (int nt = 0; nt < 16; nt++)
        #pragma unroll
        for (int f = 0; f < 4; f++) o[nt][f] = 0.f;

    const int ktmax = 2 * qi + 2;
    copy_kv(0, 0);
    cp_commit();
    __syncthreads();   // Q tile visible to all warps

    const int prow0 = warp * 16 + g;
    const int prow1 = prow0 + 8;
    const int qrow0 = Q0 + prow0;

    for (int kt = 0; kt < ktmax; kt++) {
        if (kt + 1 < ktmax) copy_kv(kt + 1, (kt + 1) & 1);
        cp_commit();
        cp_wait1();
        __syncthreads();

        const float* Kh_s = KV + (kt & 1) * 16384;
        const float* Kl_s = Kh_s + 4096;
        const float* Vh_s = Kh_s + 8192;
        const float* Vl_s = Kh_s + 12288;

        // ---- S = Q K^T (warp tile 16 x 32) ----
        float s[4][4];
        #pragma unroll
        for (int nt = 0; nt < 4; nt++)
            #pragma unroll
            for (int f = 0; f < 4; f++) s[nt][f] = 0.f;

        #pragma unroll
        for (int ks = 0; ks < 16; ks++) {
            uint4 ah = *(const uint4*)(Qh + (warp*16 + ks) * 128 + lane * 4);
            uint4 al = *(const uint4*)(Ql + (warp*16 + ks) * 128 + lane * 4);
            #pragma unroll
            for (int nt = 0; nt < 4; nt++) {
                uint2 kbh = *(const uint2*)(Kh_s + (nt*16 + ks) * 64 + lane * 2);
                uint2 kbl = *(const uint2*)(Kl_s + (nt*16 + ks) * 64 + lane * 2);
                mma42(s[nt], ah, kbl);
                mma42(s[nt], al, kbh);
                mma42(s[nt], ah, kbh);
            }
        }

        // ---- scale + mask + online softmax ----
        const bool needMask = (kt >= 2 * qi);
        float mloc0 = -1e30f, mloc1 = -1e30f;
        #pragma unroll
        for (int nt = 0; nt < 4; nt++) {
            #pragma unroll
            for (int j = 0; j < 2; j++) {
                int col = kt*32 + nt*8 + 2*tg + j;
                float sv0 = s[nt][j]   * scale;
                float sv1 = s[nt][2+j] * scale;
                if (needMask) {
                    if (col > qrow0)     sv0 = -1e30f;
                    if (col > qrow0 + 8) sv1 = -1e30f;
                }
                s[nt][j] = sv0; s[nt][2+j] = sv1;
                mloc0 = fmaxf(mloc0, sv0);
                mloc1 = fmaxf(mloc1, sv1);
            }
        }
        mloc0 = fmaxf(mloc0, __shfl_xor_sync(0xffffffffu, mloc0, 1));
        mloc0 = fmaxf(mloc0, __shfl_xor_sync(0xffffffffu, mloc0, 2));
        mloc1 = fmaxf(mloc1, __shfl_xor_sync(0xffffffffu, mloc1, 1));
        mloc1 = fmaxf(mloc1, __shfl_xor_sync(0xffffffffu, mloc1, 2));

        float mn0 = fmaxf(m0, mloc0), mn1 = fmaxf(m1, mloc1);
        float corr0 = __expf(m0 - mn0), corr1 = __expf(m1 - mn1);
        float ls0 = 0.f, ls1 = 0.f;
        #pragma unroll
        for (int nt = 0; nt < 4; nt++) {
            #pragma unroll
            for (int j = 0; j < 2; j++) {
                float p0 = __expf(s[nt][j]   - mn0);
                float p1 = __expf(s[nt][2+j] - mn1);
                s[nt][j] = p0; s[nt][2+j] = p1;
                ls0 += p0; ls1 += p1;
            }
        }
        ls0 += __shfl_xor_sync(0xffffffffu, ls0, 1);
        ls0 += __shfl_xor_sync(0xffffffffu, ls0, 2);
        ls1 += __shfl_xor_sync(0xffffffffu, ls1, 1);
        ls1 += __shfl_xor_sync(0xffffffffu, ls1, 2);
        l0 = l0 * corr0 + ls0;  m0 = mn0;
        l1 = l1 * corr1 + ls1;  m1 = mn1;

        // rescale O accumulators
        #pragma unroll
        for (int nt = 0; nt < 16; nt++) {
            o[nt][0] *= corr0; o[nt][1] *= corr0;
            o[nt][2] *= corr1; o[nt][3] *= corr1;
        }

        // ---- split P, stage via smem (warp-private rows) ----
        #pragma unroll
        for (int nt = 0; nt < 4; nt++) {
            #pragma unroll
            for (int j = 0; j < 2; j++) {
                float hi, lo;
                split_tf32(s[nt][j], hi, lo);
                Ps2[prow0*35 + nt*8 + 2*tg + j] = make_float2(hi, lo);
                split_tf32(s[nt][2+j], hi, lo);
                Ps2[prow1*35 + nt*8 + 2*tg + j] = make_float2(hi, lo);
            }
        }
        __syncwarp();

        // ---- O += P V ----
        #pragma unroll
        for (int kp = 0; kp < 4; kp++) {
            float2 a0 = Ps2[prow0*35 + kp*8 + tg];
            float2 a1 = Ps2[prow1*35 + kp*8 + tg];
            float2 a2 = Ps2[prow0*35 + kp*8 + 4 + tg];
            float2 a3 = Ps2[prow1*35 + kp*8 + 4 + tg];
            unsigned phi[4] = { __float_as_uint(a0.x), __float_as_uint(a1.x),
                                __float_as_uint(a2.x), __float_as_uint(a3.x) };
            unsigned plo[4] = { __float_as_uint(a0.y), __float_as_uint(a1.y),
                                __float_as_uint(a2.y), __float_as_uint(a3.y) };
            #pragma unroll
            for (int nt = 0; nt < 16; nt++) {
                uint2 vh = *(const uint2*)(Vh_s + nt*256 + kp*64 + lane*2);
                uint2 vl = *(const uint2*)(Vl_s + nt*256 + kp*64 + lane*2);
                mma_tf32(o[nt], phi, (const unsigned*)&vl);
                mma_tf32(o[nt], plo, (const unsigned*)&vh);
                mma_tf32(o[nt], phi, (const unsigned*)&vh);
            }
        }
        __syncthreads();   // protect KV buffer reuse
    }

    // ---- normalize + store (row-major into g_attn layout) ----
    float inv0 = 1.0f / l0, inv1 = 1.0f / l1;
    const int b = bh >> 4, h = bh & 15;
    size_t base0 = ((size_t)b * S_ + Q0 + prow0) * D_ + h * HD_;
    size_t base1 = ((size_t)b * S_ + Q0 + prow1) * D_ + h * HD_;
    #pragma unroll
    for (int nt = 0; nt < 16; nt++) {
        *(float2*)(O + base0 + nt*8 + 2*tg) = make_float2(o[nt][0]*inv0, o[nt][1]*inv0);
        *(float2*)(O + base1 + nt*8 + 2*tg) = make_float2(o[nt][2]*inv1, o[nt][3]*inv1);
    }
}

// ---------------------------------------------------------------------------
// Launch. Inputs: x, start_pos, freqs_cis, mask, wq, wk, wv, wo
// ---------------------------------------------------------------------------
extern "C" void kernel_launch(void* const* d_in, const int* in_sizes, int n_in,
                              void* d_out, int out_size) {
    (void)in_sizes; (void)n_in; (void)out_size;
    const float* x  = (const float*)d_in[0];
    const float* fc = (const float*)d_in[2];
    const float* w[4] = { (const float*)d_in[4], (const float*)d_in[5],
                          (const float*)d_in[6], (const float*)d_in[7] };
    float* out = (float*)d_out;

    float *q, *k, *v, *attn, *xah, *xal, *oah, *oal, *wbh, *wbl;
    float *qfh, *qfl, *kfh, *kfl, *vfh, *vfl;
    cudaGetSymbolAddress((void**)&q,    g_q);
    cudaGetSymbolAddress((void**)&k,    g_k);
    cudaGetSymbolAddress((void**)&v,    g_v);
    cudaGetSymbolAddress((void**)&attn, g_attn);
    cudaGetSymbolAddress((void**)&xah,  g_xah);
    cudaGetSymbolAddress((void**)&xal,  g_xal);
    cudaGetSymbolAddress((void**)&oah,  g_oah);
    cudaGetSymbolAddress((void**)&oal,  g_oal);
    cudaGetSymbolAddress((void**)&wbh,  g_wbh);
    cudaGetSymbolAddress((void**)&wbl,  g_wbl);
    cudaGetSymbolAddress((void**)&qfh,  g_qfh);
    cudaGetSymbolAddress((void**)&qfl,  g_qfl);
    cudaGetSymbolAddress((void**)&kfh,  g_kfh);
    cudaGetSymbolAddress((void**)&kfl,  g_kfl);
    cudaGetSymbolAddress((void**)&vfh,  g_vfh);
    cudaGetSymbolAddress((void**)&vfl,  g_vfl);

    cudaFuncSetAttribute(gemm_frag_rope,
                         cudaFuncAttributeMaxDynamicSharedMemorySize, GEMM_SMEM_BYTES);
    cudaFuncSetAttribute(attention_mma,
                         cudaFuncAttributeMaxDynamicSharedMemorySize, ATT2_SMEM_BYTES);

    // Pre-split GEMM operands
    split_a_kernel<<<dim3(M_/64, D_/32), 256>>>(x, xah, xal);
    for (int i = 0; i < 4; i++)
        split_b_kernel<<<dim3(D_/64, D_/32), 256>>>(w[i],
            wbh + (size_t)i * B_FRAG_FLOATS, wbl + (size_t)i * B_FRAG_FLOATS);

    dim3 gemm_grid(M_/128, D_/128);   // (32, 16)
    gemm_frag_rope<<<gemm_grid, 256, GEMM_SMEM_BYTES>>>(xah, xal,
        wbh + 0*B_FRAG_FLOATS, wbl + 0*B_FRAG_FLOATS, q, fc, 1);
    gemm_frag_rope<<<gemm_grid, 256, GEMM_SMEM_BYTES>>>(xah, xal,
        wbh + 1*B_FRAG_FLOATS, wbl + 1*B_FRAG_FLOATS, k, fc, 1);
    gemm_frag_rope<<<gemm_grid, 256, GEMM_SMEM_BYTES>>>(xah, xal,
        wbh + 2*B_FRAG_FLOATS, wbl + 2*B_FRAG_FLOATS, v, fc, 0);

    // Split Q/K/V into attention fragment layouts
    dim3 sgrid(S_/64, HD_/32, B_*NH_);   // (32, 4, 32)
    split_q_frag<<<sgrid, 256>>>(q, qfh, qfl);
    split_k_frag<<<sgrid, 256>>>(k, kfh, kfl);
    split_v_frag<<<sgrid, 256>>>(v, vfh, vfl);

    // Tensor-core flash attention
    dim3 att_grid(S_/64, NH_, B_);    // (32, 16, 2)
    attention_mma<<<att_grid, 128, ATT2_SMEM_BYTES>>>(qfh, qfl, kfh, kfl, vfh, vfl, attn);

    // Output projection
    split_a_kernel<<<dim3(M_/64, D_/32), 256>>>(attn, oah, oal);
    gemm_frag_rope<<<gemm_grid, 256, GEMM_SMEM_BYTES>>>(oah, oal,
        wbh + 3*B_FRAG_FLOATS, wbl + 3*B_FRAG_FLOATS, out, fc, 0);
}

// round 7
// speedup vs baseline: 4.2605x; 2.1270x over previous
#include <cuda_runtime.h>
#include <cuda_bf16.h>
#include <math.h>

// Problem constants
#define B_   2
#define S_   2048
#define D_   2048
#define NH_  16
#define HD_  128
#define M_   (B_*S_)          // 4096 total rows
#define KC_N (D_/16)          // 128 k16-chunks per row
#define NK_  (D_/32)          // 64 k-iterations of BK=32

// ---------------------------------------------------------------------------
// Scratch (static device globals — no runtime allocation allowed)
// ---------------------------------------------------------------------------
__device__ float g_q[(size_t)M_ * D_];
__device__ float g_k[(size_t)M_ * D_];
__device__ float g_v[(size_t)M_ * D_];
__device__ float g_attn[(size_t)M_ * D_];

// Fragment-major pre-split bf16 operands (packed bf16x2 in u32)
// A-frag tile (16m x 16k) = 32 lanes * 4 u32; B-frag tile (8n x 16k) = 32 * 2 u32
#define A_FRAG_U32 ((size_t)(M_/16) * KC_N * 128)   // 4,194,304
#define B_FRAG_U32 ((size_t)(D_/8) * KC_N * 64)     // 2,097,152
__device__ unsigned g_xah[A_FRAG_U32], g_xal[A_FRAG_U32];
__device__ unsigned g_oah[A_FRAG_U32], g_oal[A_FRAG_U32];
__device__ unsigned g_wbh[4][B_FRAG_U32], g_wbl[4][B_FRAG_U32];

// Attention fragments, per (b,h):
// Q A-frag:   [bh 32][mt 128][kc 8][128]
// K B-frag:   [bh 32][nt 256][kc 8][64]
// V B-frag(T):[bh 32][ntd 16][kcs 128][64]
#define QF_U32 ((size_t)32 * 128 * 8 * 128)
#define KF_U32 ((size_t)32 * 256 * 8 * 64)
#define VF_U32 ((size_t)32 * 16 * 128 * 64)
__device__ unsigned g_qfh[QF_U32], g_qfl[QF_U32];
__device__ unsigned g_kfh[KF_U32], g_kfl[KF_U32];
__device__ unsigned g_vfh[VF_U32], g_vfl[VF_U32];

// ---------------------------------------------------------------------------
// bf16 helpers (3xBF16 = near-fp32 precision; drops only lo*lo ~ 2^-18)
// ---------------------------------------------------------------------------
__device__ __forceinline__ unsigned pack2(float x, float y) {
    __nv_bfloat162 t = __floats2bfloat162_rn(x, y);   // x -> low half
    return *reinterpret_cast<unsigned*>(&t);
}
__device__ __forceinline__ void split2(float x, float y, unsigned &hi, unsigned &lo) {
    float hx = __bfloat162float(__float2bfloat16_rn(x));
    float hy = __bfloat162float(__float2bfloat16_rn(y));
    hi = pack2(hx, hy);
    lo = pack2(x - hx, y - hy);
}

__device__ __forceinline__ void mma_bf16(float* c, const unsigned* a, const unsigned* b) {
    asm volatile(
        "mma.sync.aligned.m16n8k16.row.col.f32.bf16.bf16.f32 "
        "{%0,%1,%2,%3}, {%4,%5,%6,%7}, {%8,%9}, {%0,%1,%2,%3};"
        : "+f"(c[0]), "+f"(c[1]), "+f"(c[2]), "+f"(c[3])
        : "r"(a[0]), "r"(a[1]), "r"(a[2]), "r"(a[3]),
          "r"(b[0]), "r"(b[1]));
}

__device__ __forceinline__ void cp16(unsigned s, const void* g) {
    asm volatile("cp.async.cg.shared.global [%0], [%1], 16;\n" :: "r"(s), "l"(g));
}
__device__ __forceinline__ void cp_commit() {
    asm volatile("cp.async.commit_group;\n" ::: "memory");
}
__device__ __forceinline__ void cp_wait1() {
    asm volatile("cp.async.wait_group 1;\n" ::: "memory");
}

// ---------------------------------------------------------------------------
// Split kernels (row-major fp32 -> fragment-major packed bf16 hi/lo)
// ---------------------------------------------------------------------------
// A split: region 64 rows x 32 cols = 4 mtiles x 2 kchunks. grid (R/64, 64).
__global__ __launch_bounds__(256) void split_a_kernel(
    const float* __restrict__ src, unsigned* __restrict__ dhi, unsigned* __restrict__ dlo)
{
    __shared__ float S[64][33];
    const int tid = threadIdx.x;
    const int row0 = blockIdx.x * 64;
    const int col0 = blockIdx.y * 32;
    #pragma unroll
    for (int i = 0; i < 8; i++) {
        int lin = tid + i * 256;
        int r = lin >> 5, c = lin & 31;
        S[r][c] = src[(size_t)(row0 + r) * D_ + col0 + c];
    }
    __syncthreads();
    const int warp = tid >> 5, lane = tid & 31;
    const int g = lane >> 2, tg = lane & 3;
    const int mt = warp >> 1, kc = warp & 1;
    const int m0 = mt * 16, k0 = kc * 16;
    uint4 hi, lo;
    split2(S[m0 + g    ][k0 + 2*tg    ], S[m0 + g    ][k0 + 2*tg + 1], hi.x, lo.x);
    split2(S[m0 + 8 + g][k0 + 2*tg    ], S[m0 + 8 + g][k0 + 2*tg + 1], hi.y, lo.y);
    split2(S[m0 + g    ][k0 + 2*tg + 8], S[m0 + g    ][k0 + 2*tg + 9], hi.z, lo.z);
    split2(S[m0 + 8 + g][k0 + 2*tg + 8], S[m0 + 8 + g][k0 + 2*tg + 9], hi.w, lo.w);
    size_t base = ((size_t)(blockIdx.x*4 + mt) * KC_N + (blockIdx.y*2 + kc)) * 128 + lane * 4;
    *(uint4*)(dhi + base) = hi;
    *(uint4*)(dlo + base) = lo;
}

// B split (weights). region 64 n x 32 k = 8 ntiles x 2 kchunks. grid (32, 64).
__global__ __launch_bounds__(256) void split_b_kernel(
    const float* __restrict__ src, unsigned* __restrict__ dhi, unsigned* __restrict__ dlo)
{
    __shared__ float S[64][33];
    const int tid = threadIdx.x;
    const int row0 = blockIdx.x * 64;
    const int col0 = blockIdx.y * 32;
    #pragma unroll
    for (int i = 0; i < 8; i++) {
        int lin = tid + i * 256;
        int r = lin >> 5, c = lin & 31;
        S[r][c] = src[(size_t)(row0 + r) * D_ + col0 + c];
    }
    __syncthreads();
    const int warp = tid >> 5, lane = tid & 31;
    const int g = lane >> 2, tg = lane & 3;
    #pragma unroll
    for (int s = 0; s < 2; s++) {
        int t = warp * 2 + s;
        int nt = t >> 1, kc = t & 1;
        int n0 = nt * 8, k0 = kc * 16;
        uint2 hi, lo;
        split2(S[n0 + g][k0 + 2*tg    ], S[n0 + g][k0 + 2*tg + 1], hi.x, lo.x);
        split2(S[n0 + g][k0 + 2*tg + 8], S[n0 + g][k0 + 2*tg + 9], hi.y, lo.y);
        size_t base = ((size_t)(blockIdx.x*8 + nt) * KC_N + (blockIdx.y*2 + kc)) * 64 + lane * 2;
        *(uint2*)(dhi + base) = hi;
        *(uint2*)(dlo + base) = lo;
    }
}

// Q split per (b,h). grid (32, 4, 32).
__global__ __launch_bounds__(256) void split_q_frag(
    const float* __restrict__ src, unsigned* __restrict__ dhi, unsigned* __restrict__ dlo)
{
    __shared__ float S[64][33];
    const int tid = threadIdx.x;
    const int bh = blockIdx.z;
    const int b = bh >> 4, h = bh & 15;
    const int row0 = b * S_ + blockIdx.x * 64;
    const int col0 = h * HD_ + blockIdx.y * 32;
    #pragma unroll
    for (int i = 0; i < 8; i++) {
        int lin = tid + i * 256;
        int r = lin >> 5, c = lin & 31;
        S[r][c] = src[(size_t)(row0 + r) * D_ + col0 + c];
    }
    __syncthreads();
    const int warp = tid >> 5, lane = tid & 31;
    const int g = lane >> 2, tg = lane & 3;
    const int mt = warp >> 1, kc = warp & 1;
    const int m0 = mt * 16, k0 = kc * 16;
    uint4 hi, lo;
    split2(S[m0 + g    ][k0 + 2*tg    ], S[m0 + g    ][k0 + 2*tg + 1], hi.x, lo.x);
    split2(S[m0 + 8 + g][k0 + 2*tg    ], S[m0 + 8 + g][k0 + 2*tg + 1], hi.y, lo.y);
    split2(S[m0 + g    ][k0 + 2*tg + 8], S[m0 + g    ][k0 + 2*tg + 9], hi.z, lo.z);
    split2(S[m0 + 8 + g][k0 + 2*tg + 8], S[m0 + 8 + g][k0 + 2*tg + 9], hi.w, lo.w);
    size_t base = (((size_t)bh*128 + blockIdx.x*4 + mt) * 8 + (blockIdx.y*2 + kc)) * 128 + lane * 4;
    *(uint4*)(dhi + base) = hi;
    *(uint4*)(dlo + base) = lo;
}

// K split per (b,h). grid (32, 4, 32).
__global__ __launch_bounds__(256) void split_k_frag(
    const float* __restrict__ src, unsigned* __restrict__ dhi, unsigned* __restrict__ dlo)
{
    __shared__ float S[64][33];
    const int tid = threadIdx.x;
    const int bh = blockIdx.z;
    const int b = bh >> 4, h = bh & 15;
    const int row0 = b * S_ + blockIdx.x * 64;
    const int col0 = h * HD_ + blockIdx.y * 32;
    #pragma unroll
    for (int i = 0; i < 8; i++) {
        int lin = tid + i * 256;
        int r = lin >> 5, c = lin & 31;
        S[r][c] = src[(size_t)(row0 + r) * D_ + col0 + c];
    }
    __syncthreads();
    const int warp = tid >> 5, lane = tid & 31;
    const int g = lane >> 2, tg = lane & 3;
    #pragma unroll
    for (int s = 0; s < 2; s++) {
        int t = warp * 2 + s;
        int nt = t >> 1, kc = t & 1;
        int n0 = nt * 8, k0 = kc * 16;
        uint2 hi, lo;
        split2(S[n0 + g][k0 + 2*tg    ], S[n0 + g][k0 + 2*tg + 1], hi.x, lo.x);
        split2(S[n0 + g][k0 + 2*tg + 8], S[n0 + g][k0 + 2*tg + 9], hi.y, lo.y);
        size_t base = (((size_t)bh*256 + blockIdx.x*8 + nt) * 8 + (blockIdx.y*2 + kc)) * 64 + lane * 2;
        *(uint2*)(dhi + base) = hi;
        *(uint2*)(dlo + base) = lo;
    }
}

// V transposed split: B-frag with n = headdim, k = seqpos. grid (32, 4, 32).
__global__ __launch_bounds__(256) void split_v_frag(
    const float* __restrict__ src, unsigned* __restrict__ dhi, unsigned* __restrict__ dlo)
{
    __shared__ float S[64][33];
    const int tid = threadIdx.x;
    const int bh = blockIdx.z;
    const int b = bh >> 4, h = bh & 15;
    const int row0 = b * S_ + blockIdx.x * 64;   // seq
    const int col0 = h * HD_ + blockIdx.y * 32;  // headdim
    #pragma unroll
    for (int i = 0; i < 8; i++) {
        int lin = tid + i * 256;
        int r = lin >> 5, c = lin & 31;
        S[r][c] = src[(size_t)(row0 + r) * D_ + col0 + c];
    }
    __syncthreads();
    const int warp = tid >> 5, lane = tid & 31;
    const int g = lane >> 2, tg = lane & 3;
    // 16 tiles: ntl over d (4), ks over seq k-chunks (4); warp handles 2
    #pragma unroll
    for (int s = 0; s < 2; s++) {
        int t = warp * 2 + s;
        int ntl = t & 3, ks = t >> 2;
        int s0 = ks * 16, d0 = ntl * 8;
        uint2 hi, lo;
        split2(S[s0 + 2*tg    ][d0 + g], S[s0 + 2*tg + 1][d0 + g], hi.x, lo.x);
        split2(S[s0 + 2*tg + 8][d0 + g], S[s0 + 2*tg + 9][d0 + g], hi.y, lo.y);
        size_t base = (((size_t)bh*16 + blockIdx.y*4 + ntl) * 128 + (blockIdx.x*4 + ks)) * 64 + lane * 2;
        *(uint2*)(dhi + base) = hi;
        *(uint2*)(dlo + base) = lo;
    }
}

// ---------------------------------------------------------------------------
// GEMM (TN) on pre-split bf16 fragments, 3xBF16.  C[m,n] = sum_d A[m,d]*W[n,d]
// Block 128x128, BK=32 (2 k-chunks), 256 threads = 8 warps (2m x 4n).
// Fused over blockIdx.z: selects weight slab + output + rope flag.
// smem per buffer (u32): Ah[0,2048) Al[2048,4096) Bh[4096,6144) Bl[6144,8192)
// ---------------------------------------------------------------------------
#define GEMM_SMEM_BYTES (2 * 8192 * 4)   // 65536

__global__ __launch_bounds__(256) void gemm_frag_rope(
    const unsigned* __restrict__ Ahi, const unsigned* __restrict__ Alo,
    const unsigned* __restrict__ Bh_base, const unsigned* __restrict__ Bl_base,
    float* __restrict__ out0, float* __restrict__ out1, float* __restrict__ out2,
    const float* __restrict__ fc, int ropeMask)
{
    extern __shared__ unsigned smu[];
    const int z = blockIdx.z;
    const unsigned* Bhi = Bh_base + (size_t)z * B_FRAG_U32;
    const unsigned* Blo = Bl_base + (size_t)z * B_FRAG_U32;
    float* C = (z == 0) ? out0 : ((z == 1) ? out1 : out2);
    const int applyRope = (ropeMask >> z) & 1;

    const int tid  = threadIdx.x;
    const int warp = tid >> 5, lane = tid & 31;
    const int wm = warp >> 2, wn = warp & 3;
    const int g  = lane >> 2, tg = lane & 3;
    const int MT0 = blockIdx.x * 8;    // 8 mtiles per block
    const int NT0 = blockIdx.y * 16;   // 16 ntiles per block

    float acc[4][4][4];
    #pragma unroll
    for (int i = 0; i < 4; i++)
        #pragma unroll
        for (int j = 0; j < 4; j++)
            #pragma unroll
            for (int f = 0; f < 4; f++) acc[i][j][f] = 0.f;

    unsigned sbase = (unsigned)__cvta_generic_to_shared(smu);

    auto copy_tile = [&](int kt, int b) {
        unsigned soff = sbase + b * 8192u * 4u;
        // A: 16 tiles (mt*2+kc) x 128 u32 = 512 cp16 per array
        #pragma unroll
        for (int i = 0; i < 2; i++) {
            int id = tid + i * 256;
            int tile = id >> 5, pos = id & 31;
            size_t gb = ((size_t)(MT0 + (tile >> 1)) * KC_N + kt*2 + (tile & 1)) * 128 + pos * 4;
            unsigned so = soff + (unsigned)(tile * 128 + pos * 4) * 4u;
            cp16(so,               Ahi + gb);
            cp16(so + 2048u * 4u,  Alo + gb);
        }
        // B: 32 tiles (nt*2+kc) x 64 u32 = 512 cp16 per array
        #pragma unroll
        for (int i = 0; i < 2; i++) {
            int id = tid + i * 256;
            int tile = id >> 4, pos = id & 15;
            size_t gb = ((size_t)(NT0 + (tile >> 1)) * KC_N + kt*2 + (tile & 1)) * 64 + pos * 4;
            unsigned so = soff + (unsigned)(4096 + tile * 64 + pos * 4) * 4u;
            cp16(so,               Bhi + gb);
            cp16(so + 2048u * 4u,  Blo + gb);
        }
    };

    copy_tile(0, 0);
    cp_commit();

    for (int kt = 0; kt < NK_; kt++) {
        if (kt + 1 < NK_) copy_tile(kt + 1, (kt + 1) & 1);
        cp_commit();
        cp_wait1();
        __syncthreads();

        const unsigned* buf = smu + (kt & 1) * 8192;
        const uint4* As_h = (const uint4*)(buf);
        const uint4* As_l = (const uint4*)(buf + 2048);
        const uint2* Bs_h = (const uint2*)(buf + 4096);
        const uint2* Bs_l = (const uint2*)(buf + 6144);

        #pragma unroll
        for (int kc = 0; kc < 2; kc++) {
            uint4 ah[4], al[4];
            #pragma unroll
            for (int mt = 0; mt < 4; mt++) {
                int idx = ((wm*4 + mt)*2 + kc) * 32 + lane;
                ah[mt] = As_h[idx];
                al[mt] = As_l[idx];
            }
            uint2 bh[4], bl[4];
            #pragma unroll
            for (int nt = 0; nt < 4; nt++) {
                int idx = ((wn*4 + nt)*2 + kc) * 32 + lane;
                bh[nt] = Bs_h[idx];
                bl[nt] = Bs_l[idx];
            }
            #pragma unroll
            for (int mt = 0; mt < 4; mt++)
                #pragma unroll
                for (int nt = 0; nt < 4; nt++) {
                    mma_bf16(acc[mt][nt], (const unsigned*)&ah[mt], (const unsigned*)&bl[nt]);
                    mma_bf16(acc[mt][nt], (const unsigned*)&al[mt], (const unsigned*)&bh[nt]);
                    mma_bf16(acc[mt][nt], (const unsigned*)&ah[mt], (const unsigned*)&bh[nt]);
                }
        }
        __syncthreads();
    }

    // Epilogue: c0,c1=(row,2tg),(row,2tg+1); c2,c3=row+8. RoPE pair = (2tg,2tg+1).
    const int bm = blockIdx.x * 128, bn = blockIdx.y * 128;
    #pragma unroll
    for (int mt = 0; mt < 4; mt++) {
        #pragma unroll
        for (int half = 0; half < 2; half++) {
            const int m = bm + wm * 64 + mt * 16 + g + half * 8;
            const int s = m & (S_ - 1);
            #pragma unroll
            for (int nt = 0; nt < 4; nt++) {
                const int n = bn + wn * 32 + nt * 8 + 2 * tg;
                float v0 = acc[mt][nt][half * 2 + 0];
                float v1 = acc[mt][nt][half * 2 + 1];
                if (applyRope) {
                    const int j = (n & (HD_ - 1)) >> 1;
                    float c_  = fc[s * HD_ + j * 2 + 0];
                    float sn_ = fc[s * HD_ + j * 2 + 1];
                    float r0 = v0 * c_  - v1 * sn_;
                    float i0 = v0 * sn_ + v1 * c_;
                    v0 = r0; v1 = i0;
                }
                *(float2*)(C + (size_t)m * D_ + n) = make_float2(v0, v1);
            }
        }
    }
}

// ---------------------------------------------------------------------------
// Tensor-core flash attention (causal, 3xBF16).
// Grid (S/64, NH, B), 128 threads = 4 warps; warp w owns q rows [w*16, w*16+16).
// kv-tile 32, double-buffered cp.async. smem (u32):
//   Qh[0,4096) Ql[4096,8192) | KV 2x8192 [8192,24576) | PsHi [24576,25664) PsLo [25664,26752)
// 107008 bytes -> 2 CTAs/SM.
// ---------------------------------------------------------------------------
#define ATT2_SMEM_BYTES (26752 * 4)

__global__ __launch_bounds__(128) void attention_mma(
    const unsigned* __restrict__ Qh_, const unsigned* __restrict__ Ql_,
    const unsigned* __restrict__ Kh_, const unsigned* __restrict__ Kl_,
    const unsigned* __restrict__ Vh_, const unsigned* __restrict__ Vl_,
    float* __restrict__ O)
{
    extern __shared__ unsigned smu[];
    unsigned* Qh = smu;              // [mt 4][kc 8][128]
    unsigned* Ql = smu + 4096;
    unsigned* KV = smu + 8192;       // 2 x { Kh 2048 | Kl 2048 | Vh 2048 | Vl 2048 }
    unsigned* PsHi = smu + 24576;    // [64][17]
    unsigned* PsLo = smu + 25664;

    const int tid  = threadIdx.x;
    const int warp = tid >> 5, lane = tid & 31;
    const int g = lane >> 2, tg = lane & 3;
    const int qi = blockIdx.x;
    const int bh = blockIdx.z * NH_ + blockIdx.y;
    const int Q0 = qi * 64;
    const float scale = 0.08838834764831845f;   // 1/sqrt(128)

    // Load Q tile fragments (4096 u32 per array, contiguous)
    {
        size_t qbase = ((size_t)bh * 128 + qi * 4) * 1024;
        const uint4* srch = (const uint4*)(Qh_ + qbase);
        const uint4* srcl = (const uint4*)(Ql_ + qbase);
        for (int i = tid; i < 1024; i += 128) {
            ((uint4*)Qh)[i] = srch[i];
            ((uint4*)Ql)[i] = srcl[i];
        }
    }

    unsigned kvbase = (unsigned)__cvta_generic_to_shared(KV);

    auto copy_kv = [&](int kt, int b) {
        unsigned soff = kvbase + (unsigned)b * 8192u * 4u;
        // K: 4 ntiles x 8 kc x 64 u32 = 2048 contiguous in global
        size_t kbase = ((size_t)bh * 256 + kt * 4) * 512;
        for (int i = tid; i < 512; i += 128) {
            cp16(soff + i * 16u,               Kh_ + kbase + i * 4);
            cp16(soff + 2048u*4u + i * 16u,    Kl_ + kbase + i * 4);
        }
        // V: 16 ntiles x 2 kcs x 64 u32
        for (int i = tid; i < 512; i += 128) {
            int tile = i >> 4, pos = i & 15;   // tile = nt*2+kc
            size_t vb = (((size_t)bh * 16 + (tile >> 1)) * 128 + (size_t)kt * 2 + (tile & 1)) * 64 + pos * 4;
            cp16(soff + 4096u*4u + i * 16u,    Vh_ + vb);
            cp16(soff + 6144u*4u + i * 16u,    Vl_ + vb);
        }
    };

    float m0 = -1e30f, m1 = -1e30f, l0 = 0.f, l1 = 0.f;
    float o[16][4];
    #pragma unroll
    for (int nt = 0; nt < 16; nt++)
        #pragma unroll
        for (int f = 0; f < 4; f++) o[nt][f] = 0.f;

    const int ktmax = 2 * qi + 2;
    copy_kv(0, 0);
    cp_commit();
    __syncthreads();   // Q tile visible

    const int prow0 = warp * 16 + g;
    const int prow1 = prow0 + 8;
    const int qrow0 = Q0 + prow0;

    for (int kt = 0; kt < ktmax; kt++) {
        if (kt + 1 < ktmax) copy_kv(kt + 1, (kt + 1) & 1);
        cp_commit();
        cp_wait1();
        __syncthreads();

        const unsigned* Kh_s = KV + (kt & 1) * 8192;
        const unsigned* Kl_s = Kh_s + 2048;
        const unsigned* Vh_s = Kh_s + 4096;
        const unsigned* Vl_s = Kh_s + 6144;

        // ---- S = Q K^T (warp tile 16 x 32) ----
        float s[4][4];
        #pragma unroll
        for (int nt = 0; nt < 4; nt++)
            #pragma unroll
            for (int f = 0; f < 4; f++) s[nt][f] = 0.f;

        #pragma unroll
        for (int kc = 0; kc < 8; kc++) {
            uint4 ah = *(const uint4*)(Qh + (warp*8 + kc) * 128 + lane * 4);
            uint4 al = *(const uint4*)(Ql + (warp*8 + kc) * 128 + lane * 4);
            #pragma unroll
            for (int nt = 0; nt < 4; nt++) {
                uint2 kbh = *(const uint2*)(Kh_s + (nt*8 + kc) * 64 + lane * 2);
                uint2 kbl = *(const uint2*)(Kl_s + (nt*8 + kc) * 64 + lane * 2);
                mma_bf16(s[nt], (const unsigned*)&ah, (const unsigned*)&kbl);
                mma_bf16(s[nt], (const unsigned*)&al, (const unsigned*)&kbh);
                mma_bf16(s[nt], (const unsigned*)&ah, (const unsigned*)&kbh);
            }
        }

        // ---- scale + mask + online softmax ----
        const bool needMask = (kt >= 2 * qi);
        float mloc0 = -1e30f, mloc1 = -1e30f;
        #pragma unroll
        for (int nt = 0; nt < 4; nt++) {
            #pragma unroll
            for (int j = 0; j < 2; j++) {
                int col = kt*32 + nt*8 + 2*tg + j;
                float sv0 = s[nt][j]   * scale;
                float sv1 = s[nt][2+j] * scale;
                if (needMask) {
                    if (col > qrow0)     sv0 = -1e30f;
                    if (col > qrow0 + 8) sv1 = -1e30f;
                }
                s[nt][j] = sv0; s[nt][2+j] = sv1;
                mloc0 = fmaxf(mloc0, sv0);
                mloc1 = fmaxf(mloc1, sv1);
            }
        }
        mloc0 = fmaxf(mloc0, __shfl_xor_sync(0xffffffffu, mloc0, 1));
        mloc0 = fmaxf(mloc0, __shfl_xor_sync(0xffffffffu, mloc0, 2));
        mloc1 = fmaxf(mloc1, __shfl_xor_sync(0xffffffffu, mloc1, 1));
        mloc1 = fmaxf(mloc1, __shfl_xor_sync(0xffffffffu, mloc1, 2));

        float mn0 = fmaxf(m0, mloc0), mn1 = fmaxf(m1, mloc1);
        float corr0 = __expf(m0 - mn0), corr1 = __expf(m1 - mn1);
        float ls0 = 0.f, ls1 = 0.f;
        #pragma unroll
        for (int nt = 0; nt < 4; nt++) {
            #pragma unroll
            for (int j = 0; j < 2; j++) {
                float p0 = __expf(s[nt][j]   - mn0);
                float p1 = __expf(s[nt][2+j] - mn1);
                s[nt][j] = p0; s[nt][2+j] = p1;
                ls0 += p0; ls1 += p1;
            }
        }
        ls0 += __shfl_xor_sync(0xffffffffu, ls0, 1);
        ls0 += __shfl_xor_sync(0xffffffffu, ls0, 2);
        ls1 += __shfl_xor_sync(0xffffffffu, ls1, 1);
        ls1 += __shfl_xor_sync(0xffffffffu, ls1, 2);
        l0 = l0 * corr0 + ls0;  m0 = mn0;
        l1 = l1 * corr1 + ls1;  m1 = mn1;

        #pragma unroll
        for (int nt = 0; nt < 16; nt++) {
            o[nt][0] *= corr0; o[nt][1] *= corr0;
            o[nt][2] *= corr1; o[nt][3] *= corr1;
        }

        // ---- split P to packed bf16, stage (warp-private rows) ----
        #pragma unroll
        for (int nt = 0; nt < 4; nt++) {
            unsigned hi, lo;
            split2(s[nt][0], s[nt][1], hi, lo);
            PsHi[prow0*17 + nt*4 + tg] = hi;
            PsLo[prow0*17 + nt*4 + tg] = lo;
            split2(s[nt][2], s[nt][3], hi, lo);
            PsHi[prow1*17 + nt*4 + tg] = hi;
            PsLo[prow1*17 + nt*4 + tg] = lo;
        }
        __syncwarp();

        // ---- O += P V ----
        #pragma unroll
        for (int kc = 0; kc < 2; kc++) {
            unsigned phi[4] = { PsHi[prow0*17 + kc*8 + tg],     PsHi[prow1*17 + kc*8 + tg],
                                PsHi[prow0*17 + kc*8 + 4 + tg], PsHi[prow1*17 + kc*8 + 4 + tg] };
            unsigned plo[4] = { PsLo[prow0*17 + kc*8 + tg],     PsLo[prow1*17 + kc*8 + tg],
                                PsLo[prow0*17 + kc*8 + 4 + tg], PsLo[prow1*17 + kc*8 + 4 + tg] };
            #pragma unroll
            for (int nt = 0; nt < 16; nt++) {
                uint2 vh = *(const uint2*)(Vh_s + (nt*2 + kc) * 64 + lane * 2);
                uint2 vl = *(const uint2*)(Vl_s + (nt*2 + kc) * 64 + lane * 2);
                mma_bf16(o[nt], phi, (const unsigned*)&vl);
                mma_bf16(o[nt], plo, (const unsigned*)&vh);
                mma_bf16(o[nt], phi, (const unsigned*)&vh);
            }
        }
        __syncthreads();   // protect KV buffer reuse
    }

    // ---- normalize + store ----
    float inv0 = 1.0f / l0, inv1 = 1.0f / l1;
    const int b = bh >> 4, h = bh & 15;
    size_t base0 = ((size_t)b * S_ + Q0 + prow0) * D_ + h * HD_;
    size_t base1 = ((size_t)b * S_ + Q0 + prow1) * D_ + h * HD_;
    #pragma unroll
    for (int nt = 0; nt < 16; nt++) {
        *(float2*)(O + base0 + nt*8 + 2*tg) = make_float2(o[nt][0]*inv0, o[nt][1]*inv0);
        *(float2*)(O + base1 + nt*8 + 2*tg) = make_float2(o[nt][2]*inv1, o[nt][3]*inv1);
    }
}

// ---------------------------------------------------------------------------
// Launch. Inputs: x, start_pos, freqs_cis, mask, wq, wk, wv, wo
// ---------------------------------------------------------------------------
extern "C" void kernel_launch(void* const* d_in, const int* in_sizes, int n_in,
                              void* d_out, int out_size) {
    (void)in_sizes; (void)n_in; (void)out_size;
    const float* x  = (const float*)d_in[0];
    const float* fc = (const float*)d_in[2];
    const float* w[4] = { (const float*)d_in[4], (const float*)d_in[5],
                          (const float*)d_in[6], (const float*)d_in[7] };
    float* out = (float*)d_out;

    float *q, *k, *v, *attn;
    unsigned *xah, *xal, *oah, *oal, *wbh, *wbl;
    unsigned *qfh, *qfl, *kfh, *kfl, *vfh, *vfl;
    cudaGetSymbolAddress((void**)&q,    g_q);
    cudaGetSymbolAddress((void**)&k,    g_k);
    cudaGetSymbolAddress((void**)&v,    g_v);
    cudaGetSymbolAddress((void**)&attn, g_attn);
    cudaGetSymbolAddress((void**)&xah,  g_xah);
    cudaGetSymbolAddress((void**)&xal,  g_xal);
    cudaGetSymbolAddress((void**)&oah,  g_oah);
    cudaGetSymbolAddress((void**)&oal,  g_oal);
    cudaGetSymbolAddress((void**)&wbh,  g_wbh);
    cudaGetSymbolAddress((void**)&wbl,  g_wbl);
    cudaGetSymbolAddress((void**)&qfh,  g_qfh);
    cudaGetSymbolAddress((void**)&qfl,  g_qfl);
    cudaGetSymbolAddress((void**)&kfh,  g_kfh);
    cudaGetSymbolAddress((void**)&kfl,  g_kfl);
    cudaGetSymbolAddress((void**)&vfh,  g_vfh);
    cudaGetSymbolAddress((void**)&vfl,  g_vfl);

    cudaFuncSetAttribute(gemm_frag_rope,
                         cudaFuncAttributeMaxDynamicSharedMemorySize, GEMM_SMEM_BYTES);
    cudaFuncSetAttribute(attention_mma,
                         cudaFuncAttributeMaxDynamicSharedMemorySize, ATT2_SMEM_BYTES);

    // Pre-split operands
    split_a_kernel<<<dim3(M_/64, D_/32), 256>>>(x, xah, xal);
    for (int i = 0; i < 4; i++)
        split_b_kernel<<<dim3(D_/64, D_/32), 256>>>(w[i],
            wbh + (size_t)i * B_FRAG_U32, wbl + (size_t)i * B_FRAG_U32);

    // Fused Q/K/V projections (z selects weight slab + output; rope on z=0,1)
    dim3 gemm_grid(M_/128, D_/128, 3);   // (32, 16, 3)
    gemm_frag_rope<<<gemm_grid, 256, GEMM_SMEM_BYTES>>>(xah, xal, wbh, wbl,
        q, k, v, fc, 0b011);

    // Split Q/K/V into attention fragment layouts
    dim3 sgrid(S_/64, HD_/32, B_*NH_);   // (32, 4, 32)
    split_q_frag<<<sgrid, 256>>>(q, qfh, qfl);
    split_k_frag<<<sgrid, 256>>>(k, kfh, kfl);
    split_v_frag<<<sgrid, 256>>>(v, vfh, vfl);

    // Tensor-core flash attention
    dim3 att_grid(S_/64, NH_, B_);       // (32, 16, 2)
    attention_mma<<<att_grid, 128, ATT2_SMEM_BYTES>>>(qfh, qfl, kfh, kfl, vfh, vfl, attn);

    // Output projection
    split_a_kernel<<<dim3(M_/64, D_/32), 256>>>(attn, oah, oal);
    dim3 o_grid(M_/128, D_/128, 1);
    gemm_frag_rope<<<o_grid, 256, GEMM_SMEM_BYTES>>>(oah, oal,
        wbh + 3*B_FRAG_U32, wbl + 3*B_FRAG_U32, out, out, out, fc, 0);
}

// round 10
// speedup vs baseline: 4.2983x; 1.0089x over previous
#include <cuda_runtime.h>
#include <cuda_bf16.h>
#include <math.h>

// Problem constants
#define B_   2
#define S_   2048
#define D_   2048
#define NH_  16
#define HD_  128
#define M_   (B_*S_)          // 4096 total rows
#define KC_N (D_/16)          // 128 k16-chunks per row
#define NK_  (D_/32)          // 64 k-iterations of BK=32

// ---------------------------------------------------------------------------
// Scratch (static device globals — no runtime allocation allowed)
// ---------------------------------------------------------------------------
__device__ float g_q[(size_t)M_ * D_];
__device__ float g_k[(size_t)M_ * D_];
__device__ float g_v[(size_t)M_ * D_];
__device__ float g_attn[(size_t)M_ * D_];

// Fragment-major pre-split bf16 operands (packed bf16x2 in u32)
// A-frag tile (16m x 16k) = 32 lanes * 4 u32; B-frag tile (8n x 16k) = 32 * 2 u32
#define A_FRAG_U32 ((size_t)(M_/16) * KC_N * 128)   // 4,194,304
#define B_FRAG_U32 ((size_t)(D_/8) * KC_N * 64)     // 2,097,152
__device__ unsigned g_xah[A_FRAG_U32], g_xal[A_FRAG_U32];
__device__ unsigned g_oah[A_FRAG_U32], g_oal[A_FRAG_U32];
__device__ unsigned g_wbh[4][B_FRAG_U32], g_wbl[4][B_FRAG_U32];

// Attention fragments, per (b,h):
// Q A-frag:   [bh 32][mt 128][kc 8][128]
// K B-frag:   [bh 32][nt 256][kc 8][64]
// V B-frag(T):[bh 32][ntd 16][kcs 128][64]
#define QF_U32 ((size_t)32 * 128 * 8 * 128)
#define KF_U32 ((size_t)32 * 256 * 8 * 64)
#define VF_U32 ((size_t)32 * 16 * 128 * 64)
__device__ unsigned g_qfh[QF_U32], g_qfl[QF_U32];
__device__ unsigned g_kfh[KF_U32], g_kfl[KF_U32];
__device__ unsigned g_vfh[VF_U32], g_vfl[VF_U32];

// ---------------------------------------------------------------------------
// bf16 helpers (3xBF16 = near-fp32 precision; drops only lo*lo ~ 2^-18)
// ---------------------------------------------------------------------------
__device__ __forceinline__ unsigned pack2(float x, float y) {
    __nv_bfloat162 t = __floats2bfloat162_rn(x, y);   // x -> low half
    return *reinterpret_cast<unsigned*>(&t);
}
__device__ __forceinline__ void split2(float x, float y, unsigned &hi, unsigned &lo) {
    float hx = __bfloat162float(__float2bfloat16_rn(x));
    float hy = __bfloat162float(__float2bfloat16_rn(y));
    hi = pack2(hx, hy);
    lo = pack2(x - hx, y - hy);
}

__device__ __forceinline__ void mma_bf16(float* c, const unsigned* a, const unsigned* b) {
    asm volatile(
        "mma.sync.aligned.m16n8k16.row.col.f32.bf16.bf16.f32 "
        "{%0,%1,%2,%3}, {%4,%5,%6,%7}, {%8,%9}, {%0,%1,%2,%3};"
        : "+f"(c[0]), "+f"(c[1]), "+f"(c[2]), "+f"(c[3])
        : "r"(a[0]), "r"(a[1]), "r"(a[2]), "r"(a[3]),
          "r"(b[0]), "r"(b[1]));
}

__device__ __forceinline__ void cp16(unsigned s, const void* g) {
    asm volatile("cp.async.cg.shared.global [%0], [%1], 16;\n" :: "r"(s), "l"(g));
}
__device__ __forceinline__ void cp_commit() {
    asm volatile("cp.async.commit_group;\n" ::: "memory");
}
__device__ __forceinline__ void cp_wait1() {
    asm volatile("cp.async.wait_group 1;\n" ::: "memory");
}

// ---------------------------------------------------------------------------
// Split kernels (row-major fp32 -> fragment-major packed bf16 hi/lo)
// ---------------------------------------------------------------------------
// A split: region 64 rows x 32 cols = 4 mtiles x 2 kchunks. grid (R/64, 64).
__global__ __launch_bounds__(256) void split_a_kernel(
    const float* __restrict__ src, unsigned* __restrict__ dhi, unsigned* __restrict__ dlo)
{
    __shared__ float S[64][33];
    const int tid = threadIdx.x;
    const int row0 = blockIdx.x * 64;
    const int col0 = blockIdx.y * 32;
    #pragma unroll
    for (int i = 0; i < 8; i++) {
        int lin = tid + i * 256;
        int r = lin >> 5, c = lin & 31;
        S[r][c] = src[(size_t)(row0 + r) * D_ + col0 + c];
    }
    __syncthreads();
    const int warp = tid >> 5, lane = tid & 31;
    const int g = lane >> 2, tg = lane & 3;
    const int mt = warp >> 1, kc = warp & 1;
    const int m0 = mt * 16, k0 = kc * 16;
    uint4 hi, lo;
    split2(S[m0 + g    ][k0 + 2*tg    ], S[m0 + g    ][k0 + 2*tg + 1], hi.x, lo.x);
    split2(S[m0 + 8 + g][k0 + 2*tg    ], S[m0 + 8 + g][k0 + 2*tg + 1], hi.y, lo.y);
    split2(S[m0 + g    ][k0 + 2*tg + 8], S[m0 + g    ][k0 + 2*tg + 9], hi.z, lo.z);
    split2(S[m0 + 8 + g][k0 + 2*tg + 8], S[m0 + 8 + g][k0 + 2*tg + 9], hi.w, lo.w);
    size_t base = ((size_t)(blockIdx.x*4 + mt) * KC_N + (blockIdx.y*2 + kc)) * 128 + lane * 4;
    *(uint4*)(dhi + base) = hi;
    *(uint4*)(dlo + base) = lo;
}

// B split (weights, BATCHED over 4 slabs via blockIdx.z). grid (32, 64, 4).
__global__ __launch_bounds__(256) void split_b_kernel(
    const float* __restrict__ w0, const float* __restrict__ w1,
    const float* __restrict__ w2, const float* __restrict__ w3,
    unsigned* __restrict__ dhi_base, unsigned* __restrict__ dlo_base)
{
    __shared__ float S[64][33];
    const int tid = threadIdx.x;
    const int z = blockIdx.z;
    const float* src = (z == 0) ? w0 : (z == 1) ? w1 : (z == 2) ? w2 : w3;
    unsigned* dhi = dhi_base + (size_t)z * B_FRAG_U32;
    unsigned* dlo = dlo_base + (size_t)z * B_FRAG_U32;
    const int row0 = blockIdx.x * 64;
    const int col0 = blockIdx.y * 32;
    #pragma unroll
    for (int i = 0; i < 8; i++) {
        int lin = tid + i * 256;
        int r = lin >> 5, c = lin & 31;
        S[r][c] = src[(size_t)(row0 + r) * D_ + col0 + c];
    }
    __syncthreads();
    const int warp = tid >> 5, lane = tid & 31;
    const int g = lane >> 2, tg = lane & 3;
    #pragma unroll
    for (int it = 0; it < 2; it++) {
        int t = warp * 2 + it;
        int nt = t >> 1, kc = t & 1;
        int n0 = nt * 8, k0 = kc * 16;
        uint2 hi, lo;
        split2(S[n0 + g][k0 + 2*tg    ], S[n0 + g][k0 + 2*tg + 1], hi.x, lo.x);
        split2(S[n0 + g][k0 + 2*tg + 8], S[n0 + g][k0 + 2*tg + 9], hi.y, lo.y);
        size_t base = ((size_t)(blockIdx.x*8 + nt) * KC_N + (blockIdx.y*2 + kc)) * 64 + lane * 2;
        *(uint2*)(dhi + base) = hi;
        *(uint2*)(dlo + base) = lo;
    }
}

// Q split per (b,h). grid (32, 4, 32).
__global__ __launch_bounds__(256) void split_q_frag(
    const float* __restrict__ src, unsigned* __restrict__ dhi, unsigned* __restrict__ dlo)
{
    __shared__ float S[64][33];
    const int tid = threadIdx.x;
    const int bh = blockIdx.z;
    const int b = bh >> 4, h = bh & 15;
    const int row0 = b * S_ + blockIdx.x * 64;
    const int col0 = h * HD_ + blockIdx.y * 32;
    #pragma unroll
    for (int i = 0; i < 8; i++) {
        int lin = tid + i * 256;
        int r = lin >> 5, c = lin & 31;
        S[r][c] = src[(size_t)(row0 + r) * D_ + col0 + c];
    }
    __syncthreads();
    const int warp = tid >> 5, lane = tid & 31;
    const int g = lane >> 2, tg = lane & 3;
    const int mt = warp >> 1, kc = warp & 1;
    const int m0 = mt * 16, k0 = kc * 16;
    uint4 hi, lo;
    split2(S[m0 + g    ][k0 + 2*tg    ], S[m0 + g    ][k0 + 2*tg + 1], hi.x, lo.x);
    split2(S[m0 + 8 + g][k0 + 2*tg    ], S[m0 + 8 + g][k0 + 2*tg + 1], hi.y, lo.y);
    split2(S[m0 + g    ][k0 + 2*tg + 8], S[m0 + g    ][k0 + 2*tg + 9], hi.z, lo.z);
    split2(S[m0 + 8 + g][k0 + 2*tg + 8], S[m0 + 8 + g][k0 + 2*tg + 9], hi.w, lo.w);
    size_t base = (((size_t)bh*128 + blockIdx.x*4 + mt) * 8 + (blockIdx.y*2 + kc)) * 128 + lane * 4;
    *(uint4*)(dhi + base) = hi;
    *(uint4*)(dlo + base) = lo;
}

// K split per (b,h). grid (32, 4, 32).
__global__ __launch_bounds__(256) void split_k_frag(
    const float* __restrict__ src, unsigned* __restrict__ dhi, unsigned* __restrict__ dlo)
{
    __shared__ float S[64][33];
    const int tid = threadIdx.x;
    const int bh = blockIdx.z;
    const int b = bh >> 4, h = bh & 15;
    const int row0 = b * S_ + blockIdx.x * 64;
    const int col0 = h * HD_ + blockIdx.y * 32;
    #pragma unroll
    for (int i = 0; i < 8; i++) {
        int lin = tid + i * 256;
        int r = lin >> 5, c = lin & 31;
        S[r][c] = src[(size_t)(row0 + r) * D_ + col0 + c];
    }
    __syncthreads();
    const int warp = tid >> 5, lane = tid & 31;
    const int g = lane >> 2, tg = lane & 3;
    #pragma unroll
    for (int it = 0; it < 2; it++) {
        int t = warp * 2 + it;
        int nt = t >> 1, kc = t & 1;
        int n0 = nt * 8, k0 = kc * 16;
        uint2 hi, lo;
        split2(S[n0 + g][k0 + 2*tg    ], S[n0 + g][k0 + 2*tg + 1], hi.x, lo.x);
        split2(S[n0 + g][k0 + 2*tg + 8], S[n0 + g][k0 + 2*tg + 9], hi.y, lo.y);
        size_t base = (((size_t)bh*256 + blockIdx.x*8 + nt) * 8 + (blockIdx.y*2 + kc)) * 64 + lane * 2;
        *(uint2*)(dhi + base) = hi;
        *(uint2*)(dlo + base) = lo;
    }
}

// V transposed split: B-frag with n = headdim, k = seqpos. grid (32, 4, 32).
__global__ __launch_bounds__(256) void split_v_frag(
    const float* __restrict__ src, unsigned* __restrict__ dhi, unsigned* __restrict__ dlo)
{
    __shared__ float S[64][33];
    const int tid = threadIdx.x;
    const int bh = blockIdx.z;
    const int b = bh >> 4, h = bh & 15;
    const int row0 = b * S_ + blockIdx.x * 64;   // seq
    const int col0 = h * HD_ + blockIdx.y * 32;  // headdim
    #pragma unroll
    for (int i = 0; i < 8; i++) {
        int lin = tid + i * 256;
        int r = lin >> 5, c = lin & 31;
        S[r][c] = src[(size_t)(row0 + r) * D_ + col0 + c];
    }
    __syncthreads();
    const int warp = tid >> 5, lane = tid & 31;
    const int g = lane >> 2, tg = lane & 3;
    #pragma unroll
    for (int it = 0; it < 2; it++) {
        int t = warp * 2 + it;
        int ntl = t & 3, ks = t >> 2;
        int s0 = ks * 16, d0 = ntl * 8;
        uint2 hi, lo;
        split2(S[s0 + 2*tg    ][d0 + g], S[s0 + 2*tg + 1][d0 + g], hi.x, lo.x);
        split2(S[s0 + 2*tg + 8][d0 + g], S[s0 + 2*tg + 9][d0 + g], hi.y, lo.y);
        size_t base = (((size_t)bh*16 + blockIdx.y*4 + ntl) * 128 + (blockIdx.x*4 + ks)) * 64 + lane * 2;
        *(uint2*)(dhi + base) = hi;
        *(uint2*)(dlo + base) = lo;
    }
}

// ---------------------------------------------------------------------------
// GEMM (TN) on pre-split bf16 fragments, 3xBF16.  C[m,n] = sum_d A[m,d]*W[n,d]
// Block 128x128, BK=32 (2 k-chunks), 256 threads = 8 warps (2m x 4n).
// Fused over blockIdx.z: selects weight slab + output + rope flag.
// smem per buffer (u32): Ah[0,2048) Al[2048,4096) Bh[4096,6144) Bl[6144,8192)
// ---------------------------------------------------------------------------
#define GEMM_SMEM_BYTES (2 * 8192 * 4)   // 65536

__global__ __launch_bounds__(256) void gemm_frag_rope(
    const unsigned* __restrict__ Ahi, const unsigned* __restrict__ Alo,
    const unsigned* __restrict__ Bh_base, const unsigned* __restrict__ Bl_base,
    float* __restrict__ out0, float* __restrict__ out1, float* __restrict__ out2,
    const float* __restrict__ fc, int ropeMask)
{
    extern __shared__ unsigned smu[];
    const int z = blockIdx.z;
    const unsigned* Bhi = Bh_base + (size_t)z * B_FRAG_U32;
    const unsigned* Blo = Bl_base + (size_t)z * B_FRAG_U32;
    float* C = (z == 0) ? out0 : ((z == 1) ? out1 : out2);
    const int applyRope = (ropeMask >> z) & 1;

    const int tid  = threadIdx.x;
    const int warp = tid >> 5, lane = tid & 31;
    const int wm = warp >> 2, wn = warp & 3;
    const int g  = lane >> 2, tg = lane & 3;
    const int MT0 = blockIdx.x * 8;    // 8 mtiles per block
    const int NT0 = blockIdx.y * 16;   // 16 ntiles per block

    float acc[4][4][4];
    #pragma unroll
    for (int i = 0; i < 4; i++)
        #pragma unroll
        for (int j = 0; j < 4; j++)
            #pragma unroll
            for (int f = 0; f < 4; f++) acc[i][j][f] = 0.f;

    unsigned sbase = (unsigned)__cvta_generic_to_shared(smu);

    auto copy_tile = [&](int kt, int b) {
        unsigned soff = sbase + b * 8192u * 4u;
        // A: 16 tiles (mt*2+kc) x 128 u32 = 512 cp16 per array
        #pragma unroll
        for (int i = 0; i < 2; i++) {
            int id = tid + i * 256;
            int tile = id >> 5, pos = id & 31;
            size_t gb = ((size_t)(MT0 + (tile >> 1)) * KC_N + kt*2 + (tile & 1)) * 128 + pos * 4;
            unsigned so = soff + (unsigned)(tile * 128 + pos * 4) * 4u;
            cp16(so,               Ahi + gb);
            cp16(so + 2048u * 4u,  Alo + gb);
        }
        // B: 32 tiles (nt*2+kc) x 64 u32 = 512 cp16 per array
        #pragma unroll
        for (int i = 0; i < 2; i++) {
            int id = tid + i * 256;
            int tile = id >> 4, pos = id & 15;
            size_t gb = ((size_t)(NT0 + (tile >> 1)) * KC_N + kt*2 + (tile & 1)) * 64 + pos * 4;
            unsigned so = soff + (unsigned)(4096 + tile * 64 + pos * 4) * 4u;
            cp16(so,               Bhi + gb);
            cp16(so + 2048u * 4u,  Blo + gb);
        }
    };

    copy_tile(0, 0);
    cp_commit();

    for (int kt = 0; kt < NK_; kt++) {
        if (kt + 1 < NK_) copy_tile(kt + 1, (kt + 1) & 1);
        cp_commit();
        cp_wait1();
        __syncthreads();

        const unsigned* buf = smu + (kt & 1) * 8192;
        const uint4* As_h = (const uint4*)(buf);
        const uint4* As_l = (const uint4*)(buf + 2048);
        const uint2* Bs_h = (const uint2*)(buf + 4096);
        const uint2* Bs_l = (const uint2*)(buf + 6144);

        #pragma unroll
        for (int kc = 0; kc < 2; kc++) {
            uint4 ah[4], al[4];
            #pragma unroll
            for (int mt = 0; mt < 4; mt++) {
                int idx = ((wm*4 + mt)*2 + kc) * 32 + lane;
                ah[mt] = As_h[idx];
                al[mt] = As_l[idx];
            }
            uint2 bh[4], bl[4];
            #pragma unroll
            for (int nt = 0; nt < 4; nt++) {
                int idx = ((wn*4 + nt)*2 + kc) * 32 + lane;
                bh[nt] = Bs_h[idx];
                bl[nt] = Bs_l[idx];
            }
            #pragma unroll
            for (int mt = 0; mt < 4; mt++)
                #pragma unroll
                for (int nt = 0; nt < 4; nt++) {
                    mma_bf16(acc[mt][nt], (const unsigned*)&ah[mt], (const unsigned*)&bl[nt]);
                    mma_bf16(acc[mt][nt], (const unsigned*)&al[mt], (const unsigned*)&bh[nt]);
                    mma_bf16(acc[mt][nt], (const unsigned*)&ah[mt], (const unsigned*)&bh[nt]);
                }
        }
        __syncthreads();
    }

    // Epilogue: c0,c1=(row,2tg),(row,2tg+1); c2,c3=row+8. RoPE pair = (2tg,2tg+1).
    const int bm = blockIdx.x * 128, bn = blockIdx.y * 128;
    #pragma unroll
    for (int mt = 0; mt < 4; mt++) {
        #pragma unroll
        for (int half = 0; half < 2; half++) {
            const int m = bm + wm * 64 + mt * 16 + g + half * 8;
            const int s = m & (S_ - 1);
            #pragma unroll
            for (int nt = 0; nt < 4; nt++) {
                const int n = bn + wn * 32 + nt * 8 + 2 * tg;
                float v0 = acc[mt][nt][half * 2 + 0];
                float v1 = acc[mt][nt][half * 2 + 1];
                if (applyRope) {
                    const int j = (n & (HD_ - 1)) >> 1;
                    float c_  = fc[s * HD_ + j * 2 + 0];
                    float sn_ = fc[s * HD_ + j * 2 + 1];
                    float r0 = v0 * c_  - v1 * sn_;
                    float i0 = v0 * sn_ + v1 * c_;
                    v0 = r0; v1 = i0;
                }
                *(float2*)(C + (size_t)m * D_ + n) = make_float2(v0, v1);
            }
        }
    }
}

// ---------------------------------------------------------------------------
// Tensor-core flash attention (causal, 3xBF16).
// Grid (S/64, NH, B), 128 threads = 4 warps; warp w owns q rows [w*16, w*16+16).
// kv-tile 32, double-buffered cp.async.
// qi REVERSED vs blockIdx.x: heaviest tiles scheduled first (load balance).
// ---------------------------------------------------------------------------
#define ATT2_SMEM_BYTES (26752 * 4)

__global__ __launch_bounds__(128) void attention_mma(
    const unsigned* __restrict__ Qh_, const unsigned* __restrict__ Ql_,
    const unsigned* __restrict__ Kh_, const unsigned* __restrict__ Kl_,
    const unsigned* __restrict__ Vh_, const unsigned* __restrict__ Vl_,
    float* __restrict__ O)
{
    extern __shared__ unsigned smu[];
    unsigned* Qh = smu;              // [mt 4][kc 8][128]
    unsigned* Ql = smu + 4096;
    unsigned* KV = smu + 8192;       // 2 x { Kh 2048 | Kl 2048 | Vh 2048 | Vl 2048 }
    unsigned* PsHi = smu + 24576;    // [64][17]
    unsigned* PsLo = smu + 25664;

    const int tid  = threadIdx.x;
    const int warp = tid >> 5, lane = tid & 31;
    const int g = lane >> 2, tg = lane & 3;
    const int qi = (int)gridDim.x - 1 - (int)blockIdx.x;   // heavy tiles first
    const int bh = blockIdx.z * NH_ + blockIdx.y;
    const int Q0 = qi * 64;
    const float scale = 0.08838834764831845f;   // 1/sqrt(128)

    {
        size_t qbase = ((size_t)bh * 128 + qi * 4) * 1024;
        const uint4* srch = (const uint4*)(Qh_ + qbase);
        const uint4* srcl = (const uint4*)(Ql_ + qbase);
        for (int i = tid; i < 1024; i += 128) {
            ((uint4*)Qh)[i] = srch[i];
            ((uint4*)Ql)[i] = srcl[i];
        }
    }

    unsigned kvbase = (unsigned)__cvta_generic_to_shared(KV);

    auto copy_kv = [&](int kt, int b) {
        unsigned soff = kvbase + (unsigned)b * 8192u * 4u;
        size_t kbase = ((size_t)bh * 256 + kt * 4) * 512;
        for (int i = tid; i < 512; i += 128) {
            cp16(soff + i * 16u,               Kh_ + kbase + i * 4);
            cp16(soff + 2048u*4u + i * 16u,    Kl_ + kbase + i * 4);
        }
        for (int i = tid; i < 512; i += 128) {
            int tile = i >> 4, pos = i & 15;
            size_t vb = (((size_t)bh * 16 + (tile >> 1)) * 128 + (size_t)kt * 2 + (tile & 1)) * 64 + pos * 4;
            cp16(soff + 4096u*4u + i * 16u,    Vh_ + vb);
            cp16(soff + 6144u*4u + i * 16u,    Vl_ + vb);
        }
    };

    float m0 = -1e30f, m1 = -1e30f, l0 = 0.f, l1 = 0.f;
    float o[16][4];
    #pragma unroll
    for (int nt = 0; nt < 16; nt++)
        #pragma unroll
        for (int f = 0; f < 4; f++) o[nt][f] = 0.f;

    const int ktmax = 2 * qi + 2;
    copy_kv(0, 0);
    cp_commit();
    __syncthreads();

    const int prow0 = warp * 16 + g;
    const int prow1 = prow0 + 8;
    const int qrow0 = Q0 + prow0;

    for (int kt = 0; kt < ktmax; kt++) {
        if (kt + 1 < ktmax) copy_kv(kt + 1, (kt + 1) & 1);
        cp_commit();
        cp_wait1();
        __syncthreads();

        const unsigned* Kh_s = KV + (kt & 1) * 8192;
        const unsigned* Kl_s = Kh_s + 2048;
        const unsigned* Vh_s = Kh_s + 4096;
        const unsigned* Vl_s = Kh_s + 6144;

        float s[4][4];
        #pragma unroll
        for (int nt = 0; nt < 4; nt++)
            #pragma unroll
            for (int f = 0; f < 4; f++) s[nt][f] = 0.f;

        #pragma unroll
        for (int kc = 0; kc < 8; kc++) {
            uint4 ah = *(const uint4*)(Qh + (warp*8 + kc) * 128 + lane * 4);
            uint4 al = *(const uint4*)(Ql + (warp*8 + kc) * 128 + lane * 4);
            #pragma unroll
            for (int nt = 0; nt < 4; nt++) {
                uint2 kbh = *(const uint2*)(Kh_s + (nt*8 + kc) * 64 + lane * 2);
                uint2 kbl = *(const uint2*)(Kl_s + (nt*8 + kc) * 64 + lane * 2);
                mma_bf16(s[nt], (const unsigned*)&ah, (const unsigned*)&kbl);
                mma_bf16(s[nt], (const unsigned*)&al, (const unsigned*)&kbh);
                mma_bf16(s[nt], (const unsigned*)&ah, (const unsigned*)&kbh);
            }
        }

        const bool needMask = (kt >= 2 * qi);
        float mloc0 = -1e30f, mloc1 = -1e30f;
        #pragma unroll
        for (int nt = 0; nt < 4; nt++) {
            #pragma unroll
            for (int j = 0; j < 2; j++) {
                int col = kt*32 + nt*8 + 2*tg + j;
                float sv0 = s[nt][j]   * scale;
                float sv1 = s[nt][2+j] * scale;
                if (needMask) {
                    if (col > qrow0)     sv0 = -1e30f;
                    if (col > qrow0 + 8) sv1 = -1e30f;
                }
                s[nt][j] = sv0; s[nt][2+j] = sv1;
                mloc0 = fmaxf(mloc0, sv0);
                mloc1 = fmaxf(mloc1, sv1);
            }
        }
        mloc0 = fmaxf(mloc0, __shfl_xor_sync(0xffffffffu, mloc0, 1));
        mloc0 = fmaxf(mloc0, __shfl_xor_sync(0xffffffffu, mloc0, 2));
        mloc1 = fmaxf(mloc1, __shfl_xor_sync(0xffffffffu, mloc1, 1));
        mloc1 = fmaxf(mloc1, __shfl_xor_sync(0xffffffffu, mloc1, 2));

        float mn0 = fmaxf(m0, mloc0), mn1 = fmaxf(m1, mloc1);
        float corr0 = __expf(m0 - mn0), corr1 = __expf(m1 - mn1);
        float ls0 = 0.f, ls1 = 0.f;
        #pragma unroll
        for (int nt = 0; nt < 4; nt++) {
            #pragma unroll
            for (int j = 0; j < 2; j++) {
                float p0 = __expf(s[nt][j]   - mn0);
                float p1 = __expf(s[nt][2+j] - mn1);
                s[nt][j] = p0; s[nt][2+j] = p1;
                ls0 += p0; ls1 += p1;
            }
        }
        ls0 += __shfl_xor_sync(0xffffffffu, ls0, 1);
        ls0 += __shfl_xor_sync(0xffffffffu, ls0, 2);
        ls1 += __shfl_xor_sync(0xffffffffu, ls1, 1);
        ls1 += __shfl_xor_sync(0xffffffffu, ls1, 2);
        l0 = l0 * corr0 + ls0;  m0 = mn0;
        l1 = l1 * corr1 + ls1;  m1 = mn1;

        #pragma unroll
        for (int nt = 0; nt < 16; nt++) {
            o[nt][0] *= corr0; o[nt][1] *= corr0;
            o[nt][2] *= corr1; o[nt][3] *= corr1;
        }

        #pragma unroll
        for (int nt = 0; nt < 4; nt++) {
            unsigned hi, lo;
            split2(s[nt][0], s[nt][1], hi, lo);
            PsHi[prow0*17 + nt*4 + tg] = hi;
            PsLo[prow0*17 + nt*4 + tg] = lo;
            split2(s[nt][2], s[nt][3], hi, lo);
            PsHi[prow1*17 + nt*4 + tg] = hi;
            PsLo[prow1*17 + nt*4 + tg] = lo;
        }
        __syncwarp();

        #pragma unroll
        for (int kc = 0; kc < 2; kc++) {
            unsigned phi[4] = { PsHi[prow0*17 + kc*8 + tg],     PsHi[prow1*17 + kc*8 + tg],
                                PsHi[prow0*17 + kc*8 + 4 + tg], PsHi[prow1*17 + kc*8 + 4 + tg] };
            unsigned plo[4] = { PsLo[prow0*17 + kc*8 + tg],     PsLo[prow1*17 + kc*8 + tg],
                                PsLo[prow0*17 + kc*8 + 4 + tg], PsLo[prow1*17 + kc*8 + 4 + tg] };
            #pragma unroll
            for (int nt = 0; nt < 16; nt++) {
                uint2 vh = *(const uint2*)(Vh_s + (nt*2 + kc) * 64 + lane * 2);
                uint2 vl = *(const uint2*)(Vl_s + (nt*2 + kc) * 64 + lane * 2);
                mma_bf16(o[nt], phi, (const unsigned*)&vl);
                mma_bf16(o[nt], plo, (const unsigned*)&vh);
                mma_bf16(o[nt], phi, (const unsigned*)&vh);
            }
        }
        __syncthreads();
    }

    float inv0 = 1.0f / l0, inv1 = 1.0f / l1;
    const int b = bh >> 4, h = bh & 15;
    size_t base0 = ((size_t)b * S_ + Q0 + prow0) * D_ + h * HD_;
    size_t base1 = ((size_t)b * S_ + Q0 + prow1) * D_ + h * HD_;
    #pragma unroll
    for (int nt = 0; nt < 16; nt++) {
        *(float2*)(O + base0 + nt*8 + 2*tg) = make_float2(o[nt][0]*inv0, o[nt][1]*inv0);
        *(float2*)(O + base1 + nt*8 + 2*tg) = make_float2(o[nt][2]*inv1, o[nt][3]*inv1);
    }
}

// ---------------------------------------------------------------------------
// Launch. Inputs: x, start_pos, freqs_cis, mask, wq, wk, wv, wo
// ---------------------------------------------------------------------------
extern "C" void kernel_launch(void* const* d_in, const int* in_sizes, int n_in,
                              void* d_out, int out_size) {
    (void)in_sizes; (void)n_in; (void)out_size;
    const float* x  = (const float*)d_in[0];
    const float* fc = (const float*)d_in[2];
    const float* w[4] = { (const float*)d_in[4], (const float*)d_in[5],
                          (const float*)d_in[6], (const float*)d_in[7] };
    float* out = (float*)d_out;

    float *q, *k, *v, *attn;
    unsigned *xah, *xal, *oah, *oal, *wbh, *wbl;
    unsigned *qfh, *qfl, *kfh, *kfl, *vfh, *vfl;
    cudaGetSymbolAddress((void**)&q,    g_q);
    cudaGetSymbolAddress((void**)&k,    g_k);
    cudaGetSymbolAddress((void**)&v,    g_v);
    cudaGetSymbolAddress((void**)&attn, g_attn);
    cudaGetSymbolAddress((void**)&xah,  g_xah);
    cudaGetSymbolAddress((void**)&xal,  g_xal);
    cudaGetSymbolAddress((void**)&oah,  g_oah);
    cudaGetSymbolAddress((void**)&oal,  g_oal);
    cudaGetSymbolAddress((void**)&wbh,  g_wbh);
    cudaGetSymbolAddress((void**)&wbl,  g_wbl);
    cudaGetSymbolAddress((void**)&qfh,  g_qfh);
    cudaGetSymbolAddress((void**)&qfl,  g_qfl);
    cudaGetSymbolAddress((void**)&kfh,  g_kfh);
    cudaGetSymbolAddress((void**)&kfl,  g_kfl);
    cudaGetSymbolAddress((void**)&vfh,  g_vfh);
    cudaGetSymbolAddress((void**)&vfl,  g_vfl);

    cudaFuncSetAttribute(gemm_frag_rope,
                         cudaFuncAttributeMaxDynamicSharedMemorySize, GEMM_SMEM_BYTES);
    cudaFuncSetAttribute(attention_mma,
                         cudaFuncAttributeMaxDynamicSharedMemorySize, ATT2_SMEM_BYTES);

    // Pre-split operands (weights batched into one launch)
    split_a_kernel<<<dim3(M_/64, D_/32), 256>>>(x, xah, xal);
    split_b_kernel<<<dim3(D_/64, D_/32, 4), 256>>>(w[0], w[1], w[2], w[3], wbh, wbl);

    // Fused Q/K/V projections (z selects weight slab + output; rope on z=0,1)
    dim3 gemm_grid(M_/128, D_/128, 3);   // (32, 16, 3)
    gemm_frag_rope<<<gemm_grid, 256, GEMM_SMEM_BYTES>>>(xah, xal, wbh, wbl,
        q, k, v, fc, 0b011);

    // Split Q/K/V into attention fragment layouts
    dim3 sgrid(S_/64, HD_/32, B_*NH_);   // (32, 4, 32)
    split_q_frag<<<sgrid, 256>>>(q, qfh, qfl);
    split_k_frag<<<sgrid, 256>>>(k, kfh, kfl);
    split_v_frag<<<sgrid, 256>>>(v, vfh, vfl);

    // Tensor-core flash attention (heavy tiles scheduled first)
    dim3 att_grid(S_/64, NH_, B_);       // (32, 16, 2)
    attention_mma<<<att_grid, 128, ATT2_SMEM_BYTES>>>(qfh, qfl, kfh, kfl, vfh, vfl, attn);

    // Output projection
    split_a_kernel<<<dim3(M_/64, D_/32), 256>>>(attn, oah, oal);
    dim3 o_grid(M_/128, D_/128, 1);
    gemm_frag_rope<<<o_grid, 256, GEMM_SMEM_BYTES>>>(oah, oal,
        wbh + 3*B_FRAG_U32, wbl + 3*B_FRAG_U32, out, out, out, fc, 0);
}